// round 2
// baseline (speedup 1.0000x reference)
#include <cuda_runtime.h>
#include <cstdint>
#include <cstddef>

#define NE 160000
#define NN 10000

// ---------------- scratch (device globals; no allocation allowed) ----------------
__device__ float g_EA [(size_t)NE * 256];   // edge features after each edge model
__device__ float g_EH [(size_t)NE * 256];   // edge hidden / messages / predictor hidden
__device__ float g_EA2[(size_t)NE * 256];   // layer-1 edge output (residual)
__device__ float g_S  [NN * 256];           // aggregated messages
__device__ float g_XH [NN * 256];           // node hidden
__device__ float g_X1 [NN * 256];           // node features after layer 0
__device__ float g_CNT[NN];                 // in-degree counts
__device__ int   g_SRC[NE];
__device__ int   g_DST[NE];
__device__ int   g_IS64;                    // 1 if edge_index is int64-layout

// ---------------- dtype probe: int32 vs int64 edge_index ----------------
// If int64 (little-endian) every odd 32-bit word is the high half of a value
// in [0, 10000) => zero. If int32, odd words are random node indices.
__global__ void detect_kernel(const int* __restrict__ ei32) {
    __shared__ int any_nonzero;
    if (threadIdx.x == 0) any_nonzero = 0;
    __syncthreads();
    // sample 2048 odd positions across the buffer (2*NE int32 words)
    for (int i = threadIdx.x; i < 2048; i += blockDim.x) {
        int pos = 2 * (i * (NE / 2048)) + 1;   // odd word index, in range
        if (ei32[pos] != 0) any_nonzero = 1;
    }
    __syncthreads();
    if (threadIdx.x == 0) g_IS64 = any_nonzero ? 0 : 1;
}

// ---------------- prep: convert indices, zero accumulators ----------------
__global__ void prep_kernel(const int* __restrict__ ei32) {
    int i = blockIdx.x * blockDim.x + threadIdx.x;
    int stride = gridDim.x * blockDim.x;
    const int is64 = g_IS64;
    for (int j = i; j < NN * 256; j += stride) g_S[j] = 0.f;
    for (int j = i; j < NN; j += stride) g_CNT[j] = 0.f;
    for (int j = i; j < NE; j += stride) {
        int s, d;
        if (is64) {           // int64 layout: low word at 2*j
            s = ei32[2 * j];
            d = ei32[2 * (NE + j)];
        } else {              // int32 layout
            s = ei32[j];
            d = ei32[NE + j];
        }
        s = min(max(s, 0), NN - 1);
        d = min(max(d, 0), NN - 1);
        g_SRC[j] = s;
        g_DST[j] = d;
    }
}

// ---------------- gather-GEMM: C[M,256] = act(concat(A0[idx0],A1[idx1],A2[idx2]) @ W + b) ----------------
template<bool RELU, bool HAS_RES>
__global__ __launch_bounds__(256, 2)
void gemm_gather(int M, int Ktot,
                 const float* __restrict__ A0, const int* __restrict__ I0, int w0, int ld0,
                 const float* __restrict__ A1, const int* __restrict__ I1, int w1, int ld1,
                 const float* __restrict__ A2, const int* __restrict__ I2, int w2, int ld2,
                 const float* __restrict__ W, const float* __restrict__ bias,
                 const float* __restrict__ Res, float* __restrict__ C)
{
    __shared__ float As[8][128];
    __shared__ float Bs[8][128];

    const int tid = threadIdx.x;
    const int tx = tid & 15;          // N-dir thread coord (0..15)
    const int ty = tid >> 4;          // M-dir thread coord (0..15)
    const int gm_base = blockIdx.x * 128;
    const int gn_base = blockIdx.y * 128;

    // A-tile load assignment: each thread loads 4 consecutive k for one row
    const int arow = tid >> 1;        // 0..127
    const int ak   = (tid & 1) * 4;   // 0 or 4
    const int gm   = gm_base + arow;
    const bool mvalid = gm < M;
    int r0 = 0, r1 = 0, r2 = 0;
    if (mvalid) {
        r0 = I0 ? I0[gm] : gm;
        r1 = (w1 && I1) ? I1[gm] : gm;
        r2 = (w2 && I2) ? I2[gm] : gm;
    }
    const int w01 = w0 + w1;

    // B-tile load assignment: float4 per thread
    const int bk = tid >> 5;          // 0..7
    const int bn = (tid & 31) * 4;    // 0..124

    float acc[8][8];
    #pragma unroll
    for (int i = 0; i < 8; i++)
        #pragma unroll
        for (int j = 0; j < 8; j++) acc[i][j] = 0.f;

    const int ktiles = (Ktot + 7) >> 3;
    for (int kt = 0; kt < ktiles; kt++) {
        const int k0 = kt << 3;
        // load A (gathered, segment-selected)
        #pragma unroll
        for (int j = 0; j < 4; j++) {
            const int k = k0 + ak + j;
            float v = 0.f;
            if (mvalid && k < Ktot) {
                if (k < w0)       v = A0[(size_t)r0 * ld0 + k];
                else if (k < w01) v = A1[(size_t)r1 * ld1 + (k - w0)];
                else              v = A2[(size_t)r2 * ld2 + (k - w01)];
            }
            As[ak + j][arow] = v;
        }
        // load B
        {
            const int k = k0 + bk;
            float4 v = make_float4(0.f, 0.f, 0.f, 0.f);
            if (k < Ktot) v = *(const float4*)&W[(size_t)k * 256 + gn_base + bn];
            *(float4*)&Bs[bk][bn] = v;
        }
        __syncthreads();
        #pragma unroll
        for (int kk = 0; kk < 8; kk++) {
            float a[8], b[8];
            *(float4*)&a[0] = *(const float4*)&As[kk][ty * 8];
            *(float4*)&a[4] = *(const float4*)&As[kk][ty * 8 + 4];
            *(float4*)&b[0] = *(const float4*)&Bs[kk][tx * 8];
            *(float4*)&b[4] = *(const float4*)&Bs[kk][tx * 8 + 4];
            #pragma unroll
            for (int i = 0; i < 8; i++)
                #pragma unroll
                for (int j = 0; j < 8; j++)
                    acc[i][j] += a[i] * b[j];
        }
        __syncthreads();
    }

    // epilogue: bias (+ relu) (+ residual)
    const int ccol = gn_base + tx * 8;
    float bv[8];
    *(float4*)&bv[0] = *(const float4*)&bias[ccol];
    *(float4*)&bv[4] = *(const float4*)&bias[ccol + 4];
    #pragma unroll
    for (int i = 0; i < 8; i++) {
        const int r = gm_base + ty * 8 + i;
        if (r < M) {
            float o[8];
            #pragma unroll
            for (int j = 0; j < 8; j++) {
                float v = acc[i][j] + bv[j];
                if (RELU) v = fmaxf(v, 0.f);
                o[j] = v;
            }
            if (HAS_RES) {
                float4 ra = *(const float4*)&Res[(size_t)r * 256 + ccol];
                float4 rb = *(const float4*)&Res[(size_t)r * 256 + ccol + 4];
                o[0] += ra.x; o[1] += ra.y; o[2] += ra.z; o[3] += ra.w;
                o[4] += rb.x; o[5] += rb.y; o[6] += rb.z; o[7] += rb.w;
            }
            *(float4*)&C[(size_t)r * 256 + ccol]     = *(float4*)&o[0];
            *(float4*)&C[(size_t)r * 256 + ccol + 4] = *(float4*)&o[4];
        }
    }
}

// ---------------- scatter / mean / predictor ----------------
__global__ void scatter_kernel(const float* __restrict__ EH) {
    int e = blockIdx.x;
    int d = g_DST[e];
    int c = threadIdx.x;
    atomicAdd(&g_S[d * 256 + c], EH[(size_t)e * 256 + c]);
}

__global__ void count_kernel() {
    int e = blockIdx.x * blockDim.x + threadIdx.x;
    if (e < NE) atomicAdd(&g_CNT[g_DST[e]], 1.f);
}

__global__ void mean_kernel() {
    int n = blockIdx.x;
    float c = fmaxf(g_CNT[n], 1.f);
    g_S[n * 256 + threadIdx.x] = g_S[n * 256 + threadIdx.x] / c;
}

__global__ void pred_kernel(const float* __restrict__ EH, const float* __restrict__ w2,
                            const float* __restrict__ b2, float* __restrict__ out) {
    int e = blockIdx.x * 8 + (threadIdx.x >> 5);
    int lane = threadIdx.x & 31;
    if (e >= NE) return;
    float s = 0.f;
    #pragma unroll
    for (int c = 0; c < 256; c += 32)
        s += EH[(size_t)e * 256 + c + lane] * w2[c + lane];
    #pragma unroll
    for (int o = 16; o; o >>= 1) s += __shfl_xor_sync(0xffffffffu, s, o);
    if (lane == 0) out[e] = s + b2[0];
}

// ---------------- host-side dispatch ----------------
static void run_gemm(bool relu, bool has_res, int M, int Ktot,
                     const float* A0, const int* I0, int w0, int ld0,
                     const float* A1, const int* I1, int w1, int ld1,
                     const float* A2, const int* I2, int w2, int ld2,
                     const float* W, const float* bias, const float* Res, float* C)
{
    dim3 grid((M + 127) / 128, 2), blk(256);
    if (relu)
        gemm_gather<true, false><<<grid, blk>>>(M, Ktot, A0, I0, w0, ld0, A1, I1, w1, ld1,
                                                A2, I2, w2, ld2, W, bias, Res, C);
    else if (has_res)
        gemm_gather<false, true><<<grid, blk>>>(M, Ktot, A0, I0, w0, ld0, A1, I1, w1, ld1,
                                                A2, I2, w2, ld2, W, bias, Res, C);
    else
        gemm_gather<false, false><<<grid, blk>>>(M, Ktot, A0, I0, w0, ld0, A1, I1, w1, ld1,
                                                 A2, I2, w2, ld2, W, bias, Res, C);
}

extern "C" void kernel_launch(void* const* d_in, const int* in_sizes, int n_in,
                              void* d_out, int out_size)
{
    const float* x      = (const float*)d_in[0];
    const int*   ei32   = (const int*)d_in[1];    // int32 (JAX x64 disabled); probed at runtime
    const float* eattr  = (const float*)d_in[2];
    const float* e_w1_0 = (const float*)d_in[3];
    const float* e_b1_0 = (const float*)d_in[4];
    const float* e_w2_0 = (const float*)d_in[5];
    const float* e_b2_0 = (const float*)d_in[6];
    const float* n_wm_0 = (const float*)d_in[7];
    const float* n_bm_0 = (const float*)d_in[8];
    const float* n_w1_0 = (const float*)d_in[9];
    const float* n_b1_0 = (const float*)d_in[10];
    const float* n_w2_0 = (const float*)d_in[11];
    const float* n_b2_0 = (const float*)d_in[12];
    const float* e_w1_1 = (const float*)d_in[13];
    const float* e_b1_1 = (const float*)d_in[14];
    const float* e_w2_1 = (const float*)d_in[15];
    const float* e_b2_1 = (const float*)d_in[16];
    // layer-1 node model (d_in[17..22]) is dead code: output depends only on edge path
    const float* p_w1   = (const float*)d_in[23];
    const float* p_b1   = (const float*)d_in[24];
    const float* p_w2   = (const float*)d_in[25];
    const float* p_b2   = (const float*)d_in[26];
    float* out = (float*)d_out;

    float *EA, *EH, *EA2, *S, *XH, *X1;
    int *SRC, *DST;
    cudaGetSymbolAddress((void**)&EA,  g_EA);
    cudaGetSymbolAddress((void**)&EH,  g_EH);
    cudaGetSymbolAddress((void**)&EA2, g_EA2);
    cudaGetSymbolAddress((void**)&S,   g_S);
    cudaGetSymbolAddress((void**)&XH,  g_XH);
    cudaGetSymbolAddress((void**)&X1,  g_X1);
    cudaGetSymbolAddress((void**)&SRC, g_SRC);
    cudaGetSymbolAddress((void**)&DST, g_DST);

    // 0) index dtype probe + conversion + zero accumulators
    detect_kernel<<<1, 256>>>(ei32);
    prep_kernel<<<2048, 256>>>(ei32);

    // ---- Layer 0 edge model ----
    // EH = relu([x[src], x[dst], ea] @ e_w1_0 + b)   K = 512+512+6 = 1030
    run_gemm(true, false, NE, 1030,
             x, SRC, 512, 512,  x, DST, 512, 512,  eattr, nullptr, 6, 6,
             e_w1_0, e_b1_0, nullptr, EH);
    // EA = EH @ e_w2_0 + b            (no residual: 6 != 256)
    run_gemm(false, false, NE, 256,
             EH, nullptr, 256, 256,  nullptr, nullptr, 0, 0,  nullptr, nullptr, 0, 0,
             e_w2_0, e_b2_0, nullptr, EA);

    // ---- Layer 0 node model ----
    // EH = relu([x[src], EA] @ n_wm_0 + b)   K = 768
    run_gemm(true, false, NE, 768,
             x, SRC, 512, 512,  EA, nullptr, 256, 256,  nullptr, nullptr, 0, 0,
             n_wm_0, n_bm_0, nullptr, EH);
    // S = mean-scatter(EH, dst)
    scatter_kernel<<<NE, 256>>>(EH);
    count_kernel<<<(NE + 255) / 256, 256>>>();
    mean_kernel<<<NN, 256>>>();
    // XH = relu([x, S] @ n_w1_0 + b); X1 = XH @ n_w2_0 + b   (no residual: 512 != 256)
    run_gemm(true, false, NN, 768,
             x, nullptr, 512, 512,  S, nullptr, 256, 256,  nullptr, nullptr, 0, 0,
             n_w1_0, n_b1_0, nullptr, XH);
    run_gemm(false, false, NN, 256,
             XH, nullptr, 256, 256,  nullptr, nullptr, 0, 0,  nullptr, nullptr, 0, 0,
             n_w2_0, n_b2_0, nullptr, X1);

    // ---- Layer 1 edge model ----
    // EH = relu([X1[src], X1[dst], EA] @ e_w1_1 + b)   K = 768
    run_gemm(true, false, NE, 768,
             X1, SRC, 256, 256,  X1, DST, 256, 256,  EA, nullptr, 256, 256,
             e_w1_1, e_b1_1, nullptr, EH);
    // EA2 = EH @ e_w2_1 + b + EA   (residual: 256 == 256)
    run_gemm(false, true, NE, 256,
             EH, nullptr, 256, 256,  nullptr, nullptr, 0, 0,  nullptr, nullptr, 0, 0,
             e_w2_1, e_b2_1, EA, EA2);
    // (layer-1 node model skipped: unused by output)

    // ---- Edge predictor ----
    // EH = relu(EA2 @ p_w1 + b)
    run_gemm(true, false, NE, 256,
             EA2, nullptr, 256, 256,  nullptr, nullptr, 0, 0,  nullptr, nullptr, 0, 0,
             p_w1, p_b1, nullptr, EH);
    // out = EH @ p_w2 + b2  (fused warp-per-edge reduction)
    pred_kernel<<<NE / 8, 256>>>(EH, p_w2, p_b2, out);

    (void)in_sizes; (void)n_in; (void)out_size;
}

// round 4
// speedup vs baseline: 2.6099x; 2.6099x over previous
#include <cuda_runtime.h>
#include <cuda_bf16.h>
#include <cstdint>
#include <cstddef>

#define NE 160000
#define NN 10000

// ---------------- scratch (device globals) ----------------
__device__ float g_EA [(size_t)NE * 256];
__device__ float g_EH [(size_t)NE * 256];
__device__ float g_EA2[(size_t)NE * 256];
__device__ float g_S  [NN * 256];
__device__ float g_XH [NN * 256];
__device__ float g_X1 [NN * 256];
__device__ float g_CNT[NN];
__device__ int   g_SRC[NE];
__device__ int   g_DST[NE];
__device__ int   g_IS64;
// pre-split/transposed weights: [n(256)][Kpad] bf16 hi/lo, concatenated per-GEMM
__device__ __nv_bfloat16 g_WTH[256 * 4416];
__device__ __nv_bfloat16 g_WTL[256 * 4416];

// ---------------- helpers ----------------
__device__ __forceinline__ uint32_t smem_u32(const void* p) {
    uint32_t a;
    asm("{ .reg .u64 t; cvta.to.shared.u64 t, %1; cvt.u32.u64 %0, t; }" : "=r"(a) : "l"(p));
    return a;
}
__device__ __forceinline__ void sts128(uint32_t addr, uint32_t a, uint32_t b, uint32_t c, uint32_t d) {
    asm volatile("st.shared.v4.b32 [%0], {%1,%2,%3,%4};" :: "r"(addr), "r"(a), "r"(b), "r"(c), "r"(d) : "memory");
}
__device__ __forceinline__ void ldsm4(uint32_t* r, uint32_t addr) {
    asm volatile("ldmatrix.sync.aligned.m8n8.x4.shared.b16 {%0,%1,%2,%3}, [%4];"
                 : "=r"(r[0]), "=r"(r[1]), "=r"(r[2]), "=r"(r[3]) : "r"(addr));
}
__device__ __forceinline__ void mma_bf16(float* d, const uint32_t* a, uint32_t b0, uint32_t b1) {
    asm volatile(
        "mma.sync.aligned.m16n8k16.row.col.f32.bf16.bf16.f32 "
        "{%0,%1,%2,%3}, {%4,%5,%6,%7}, {%8,%9}, {%0,%1,%2,%3};"
        : "+f"(d[0]), "+f"(d[1]), "+f"(d[2]), "+f"(d[3])
        : "r"(a[0]), "r"(a[1]), "r"(a[2]), "r"(a[3]), "r"(b0), "r"(b1));
}

// ---------------- weight pre-split/transpose ----------------
__global__ void wt_kernel(const float* __restrict__ W, int K, int Kpad,
                          __nv_bfloat16* __restrict__ H, __nv_bfloat16* __restrict__ L) {
    int idx = blockIdx.x * blockDim.x + threadIdx.x;
    if (idx >= 256 * Kpad) return;
    int n = idx / Kpad, k = idx - n * Kpad;
    float v = (k < K) ? W[(size_t)k * 256 + n] : 0.f;
    uint32_t b = __float_as_uint(v);
    uint32_t hb = b & 0xFFFF0000u;
    ((unsigned short*)H)[idx] = (unsigned short)(hb >> 16);
    L[idx] = __float2bfloat16_rn(v - __uint_as_float(hb));
}

// ---------------- index dtype probe + prep ----------------
__global__ void detect_kernel(const int* __restrict__ ei32) {
    __shared__ int any_nonzero;
    if (threadIdx.x == 0) any_nonzero = 0;
    __syncthreads();
    for (int i = threadIdx.x; i < 2048; i += blockDim.x) {
        int pos = 2 * (i * (NE / 2048)) + 1;
        if (ei32[pos] != 0) any_nonzero = 1;
    }
    __syncthreads();
    if (threadIdx.x == 0) g_IS64 = any_nonzero ? 0 : 1;
}

__global__ void prep_kernel(const int* __restrict__ ei32) {
    int i = blockIdx.x * blockDim.x + threadIdx.x;
    int stride = gridDim.x * blockDim.x;
    const int is64 = g_IS64;
    for (int j = i; j < NN * 256; j += stride) g_S[j] = 0.f;
    for (int j = i; j < NN; j += stride) g_CNT[j] = 0.f;
    for (int j = i; j < NE; j += stride) {
        int s, d;
        if (is64) { s = ei32[2 * j]; d = ei32[2 * (NE + j)]; }
        else      { s = ei32[j];     d = ei32[NE + j]; }
        g_SRC[j] = min(max(s, 0), NN - 1);
        g_DST[j] = min(max(d, 0), NN - 1);
    }
}

__global__ void count_kernel() {
    int e = blockIdx.x * blockDim.x + threadIdx.x;
    if (e < NE) atomicAdd(&g_CNT[g_DST[e]], 1.f);
}

// ---------------- HMMA gather-GEMM ----------------
// C[M,256] = act(concat(A0[i0],A1[i1],A2[row]) @ W + b) (+Res)
// Tile: CTA 128x128, warp 32x64, m16n8k16 bf16 3-pass split, fp32 accum.
#define RS 40   // smem row stride in bf16 elems (80 bytes)

template<bool RELU, bool HAS_RES>
__global__ void __launch_bounds__(256, 2) gemm_hmma(
    int M, int Ktot, int nch,
    const float* __restrict__ A0, const int* __restrict__ I0, int w0, int ld0,
    const float* __restrict__ A1, const int* __restrict__ I1, int w1, int ld1,
    const float* __restrict__ A2, int ld2,
    const __nv_bfloat16* __restrict__ WtH, const __nv_bfloat16* __restrict__ WtL, int Kpad,
    const float* __restrict__ bias, const float* __restrict__ Res, float* __restrict__ C)
{
    __shared__ __align__(16) unsigned short sAh[128 * RS], sAl[128 * RS];
    __shared__ __align__(16) unsigned short sBh[128 * RS], sBl[128 * RS];

    const int tid = threadIdx.x;
    const int lane = tid & 31, wid = tid >> 5;
    const int warp_m = wid & 3, warp_n = wid >> 2;
    const int bm = blockIdx.x * 128;
    const int gn = blockIdx.y * 128;
    const int w01 = w0 + w1;

    const uint32_t bAh = smem_u32(sAh), bAl = smem_u32(sAl);
    const uint32_t bBh = smem_u32(sBh), bBl = smem_u32(sBl);

    // gather row indices: one A-row per 2 threads (fixed across chunks)
    const int arow = tid >> 1;
    const int kh = (tid & 1) * 16;
    const int gmc = min(bm + arow, M - 1);
    const int r0i = I0 ? I0[gmc] : gmc;
    const int r1i = (w1 && I1) ? I1[gmc] : gmc;
    const int r2i = gmc;
    const bool ld2ok = ((ld2 & 3) == 0);

    float acc[2][8][4];
    #pragma unroll
    for (int a = 0; a < 2; a++)
        #pragma unroll
        for (int b = 0; b < 8; b++)
            #pragma unroll
            for (int c = 0; c < 4; c++) acc[a][b][c] = 0.f;

    for (int c = 0; c < nch; c++) {
        const int k0 = c << 5;

        // ---- A fill: gather 16 fp32, split hi/lo bf16 ----
        {
            const int kb = k0 + kh;
            float vv[16];
            const float* p = nullptr;
            if (kb + 16 <= w0)        p = A0 + (size_t)r0i * ld0 + kb;
            else if (kb + 16 <= w01)  p = A1 + (size_t)r1i * ld1 + (kb - w0);
            else if (kb + 16 <= Ktot && ld2ok) p = A2 + (size_t)r2i * ld2 + (kb - w01);
            if (p) {
                #pragma unroll
                for (int j = 0; j < 4; j++)
                    *(float4*)&vv[4 * j] = ((const float4*)p)[j];
            } else {
                #pragma unroll
                for (int j = 0; j < 16; j++) {
                    int k = kb + j;
                    float x = 0.f;
                    if (k < Ktot) {
                        if (k < w0)       x = A0[(size_t)r0i * ld0 + k];
                        else if (k < w01) x = A1[(size_t)r1i * ld1 + k - w0];
                        else              x = A2[(size_t)r2i * ld2 + k - w01];
                    }
                    vv[j] = x;
                }
            }
            uint32_t hw[8], lw[8];
            #pragma unroll
            for (int j = 0; j < 8; j++) {
                float a = vv[2 * j], b = vv[2 * j + 1];
                uint32_t ba = __float_as_uint(a), bb = __float_as_uint(b);
                hw[j] = (bb & 0xFFFF0000u) | (ba >> 16);
                float la = a - __uint_as_float(ba & 0xFFFF0000u);
                float lb = b - __uint_as_float(bb & 0xFFFF0000u);
                asm("cvt.rn.bf16x2.f32 %0, %1, %2;" : "=r"(lw[j]) : "f"(lb), "f"(la));
            }
            uint32_t off = (uint32_t)arow * (RS * 2) + kh * 2;
            sts128(bAh + off,      hw[0], hw[1], hw[2], hw[3]);
            sts128(bAh + off + 16, hw[4], hw[5], hw[6], hw[7]);
            sts128(bAl + off,      lw[0], lw[1], lw[2], lw[3]);
            sts128(bAl + off + 16, lw[4], lw[5], lw[6], lw[7]);
        }

        // ---- B fill: pre-split bf16 straight copy ----
        {
            const int brow = tid >> 1;
            const size_t src = (size_t)(gn + brow) * Kpad + k0;
            #pragma unroll
            for (int j = 0; j < 2; j++) {
                const int seg = (tid & 1) * 2 + j;     // 0..3, each 8 bf16
                uint4 vh = *(const uint4*)(WtH + src + seg * 8);
                uint4 vl = *(const uint4*)(WtL + src + seg * 8);
                uint32_t off = (uint32_t)brow * (RS * 2) + seg * 16;
                sts128(bBh + off, vh.x, vh.y, vh.z, vh.w);
                sts128(bBl + off, vl.x, vl.y, vl.z, vl.w);
            }
        }
        __syncthreads();

        // ---- MMA: 2 k16 steps x 3 passes ----
        #pragma unroll
        for (int kk = 0; kk < 2; kk++) {
            const int k16 = kk * 16;
            uint32_t aH[2][4], aL[2][4];
            {
                const int ar = warp_m * 32 + (lane & 15);
                const int ak = k16 + ((lane >> 4) << 3);
                uint32_t off = (uint32_t)ar * (RS * 2) + ak * 2;
                ldsm4(aH[0], bAh + off);
                ldsm4(aH[1], bAh + off + 16 * (RS * 2));
                ldsm4(aL[0], bAl + off);
                ldsm4(aL[1], bAl + off + 16 * (RS * 2));
            }
            #pragma unroll
            for (int ppp = 0; ppp < 4; ppp++) {
                const int bn = warp_n * 64 + ppp * 16 + ((lane >> 4) & 1) * 8 + (lane & 7);
                const int bk = k16 + ((lane >> 3) & 1) * 8;
                uint32_t off = (uint32_t)bn * (RS * 2) + bk * 2;
                uint32_t bh[4], bl[4];
                ldsm4(bh, bBh + off);
                ldsm4(bl, bBl + off);
                #pragma unroll
                for (int mt = 0; mt < 2; mt++) {
                    mma_bf16(acc[mt][2 * ppp],     aH[mt], bh[0], bh[1]);
                    mma_bf16(acc[mt][2 * ppp],     aH[mt], bl[0], bl[1]);
                    mma_bf16(acc[mt][2 * ppp],     aL[mt], bh[0], bh[1]);
                    mma_bf16(acc[mt][2 * ppp + 1], aH[mt], bh[2], bh[3]);
                    mma_bf16(acc[mt][2 * ppp + 1], aH[mt], bl[2], bl[3]);
                    mma_bf16(acc[mt][2 * ppp + 1], aL[mt], bh[2], bh[3]);
                }
            }
        }
        __syncthreads();
    }

    // ---- epilogue ----
    const int gid = lane >> 2, tig = lane & 3;
    #pragma unroll
    for (int mt = 0; mt < 2; mt++) {
        const int rA = bm + warp_m * 32 + mt * 16 + gid;
        const int rB = rA + 8;
        #pragma unroll
        for (int nt = 0; nt < 8; nt++) {
            const int col = gn + warp_n * 64 + nt * 8 + tig * 2;
            const float b0 = bias[col], b1 = bias[col + 1];
            float* a = acc[mt][nt];
            if (rA < M) {
                float o0 = a[0] + b0, o1 = a[1] + b1;
                if (RELU) { o0 = fmaxf(o0, 0.f); o1 = fmaxf(o1, 0.f); }
                if (HAS_RES) {
                    const float2 rr = *(const float2*)&Res[(size_t)rA * 256 + col];
                    o0 += rr.x; o1 += rr.y;
                }
                *(float2*)&C[(size_t)rA * 256 + col] = make_float2(o0, o1);
            }
            if (rB < M) {
                float o0 = a[2] + b0, o1 = a[3] + b1;
                if (RELU) { o0 = fmaxf(o0, 0.f); o1 = fmaxf(o1, 0.f); }
                if (HAS_RES) {
                    const float2 rr = *(const float2*)&Res[(size_t)rB * 256 + col];
                    o0 += rr.x; o1 += rr.y;
                }
                *(float2*)&C[(size_t)rB * 256 + col] = make_float2(o0, o1);
            }
        }
    }
}

// ---------------- scatter / mean / predictor ----------------
__global__ void scatter_kernel(const float* __restrict__ EH) {
    int e = blockIdx.x;
    int d = g_DST[e];
    int c = threadIdx.x;
    atomicAdd(&g_S[d * 256 + c], EH[(size_t)e * 256 + c]);
}

__global__ void mean_kernel() {
    int n = blockIdx.x;
    float cinv = 1.f / fmaxf(g_CNT[n], 1.f);
    g_S[n * 256 + threadIdx.x] *= cinv;
}

__global__ void pred_kernel(const float* __restrict__ EH, const float* __restrict__ w2,
                            const float* __restrict__ b2, float* __restrict__ out) {
    int e = blockIdx.x * 8 + (threadIdx.x >> 5);
    int lane = threadIdx.x & 31;
    if (e >= NE) return;
    float s = 0.f;
    #pragma unroll
    for (int c = 0; c < 256; c += 32)
        s += EH[(size_t)e * 256 + c + lane] * w2[c + lane];
    #pragma unroll
    for (int o = 16; o; o >>= 1) s += __shfl_xor_sync(0xffffffffu, s, o);
    if (lane == 0) out[e] = s + b2[0];
}

// ---------------- host dispatch ----------------
static void run_tc(int mode /*0 plain,1 relu,2 res*/, int M, int Ktot, int Kpad,
                   const float* A0, const int* I0, int w0, int ld0,
                   const float* A1, const int* I1, int w1, int ld1,
                   const float* A2, int ld2,
                   const __nv_bfloat16* WtH, const __nv_bfloat16* WtL,
                   const float* bias, const float* Res, float* C)
{
    int nch = Kpad / 32;
    dim3 grid((M + 127) / 128, 2), blk(256);
    if (mode == 1)
        gemm_hmma<true, false><<<grid, blk>>>(M, Ktot, nch, A0, I0, w0, ld0,
            A1, I1, w1, ld1, A2, ld2, WtH, WtL, Kpad, bias, Res, C);
    else if (mode == 2)
        gemm_hmma<false, true><<<grid, blk>>>(M, Ktot, nch, A0, I0, w0, ld0,
            A1, I1, w1, ld1, A2, ld2, WtH, WtL, Kpad, bias, Res, C);
    else
        gemm_hmma<false, false><<<grid, blk>>>(M, Ktot, nch, A0, I0, w0, ld0,
            A1, I1, w1, ld1, A2, ld2, WtH, WtL, Kpad, bias, Res, C);
}

extern "C" void kernel_launch(void* const* d_in, const int* in_sizes, int n_in,
                              void* d_out, int out_size)
{
    const float* x      = (const float*)d_in[0];
    const int*   ei32   = (const int*)d_in[1];
    const float* eattr  = (const float*)d_in[2];
    const float* e_w1_0 = (const float*)d_in[3];
    const float* e_b1_0 = (const float*)d_in[4];
    const float* e_w2_0 = (const float*)d_in[5];
    const float* e_b2_0 = (const float*)d_in[6];
    const float* n_wm_0 = (const float*)d_in[7];
    const float* n_bm_0 = (const float*)d_in[8];
    const float* n_w1_0 = (const float*)d_in[9];
    const float* n_b1_0 = (const float*)d_in[10];
    const float* n_w2_0 = (const float*)d_in[11];
    const float* n_b2_0 = (const float*)d_in[12];
    const float* e_w1_1 = (const float*)d_in[13];
    const float* e_b1_1 = (const float*)d_in[14];
    const float* e_w2_1 = (const float*)d_in[15];
    const float* e_b2_1 = (const float*)d_in[16];
    // d_in[17..22]: layer-1 node model — dead code for the output
    const float* p_w1   = (const float*)d_in[23];
    const float* p_b1   = (const float*)d_in[24];
    const float* p_w2   = (const float*)d_in[25];
    const float* p_b2   = (const float*)d_in[26];
    float* out = (float*)d_out;

    float *EA, *EH, *EA2, *S, *XH, *X1;
    int *SRC, *DST;
    __nv_bfloat16 *WTH, *WTL;
    cudaGetSymbolAddress((void**)&EA,  g_EA);
    cudaGetSymbolAddress((void**)&EH,  g_EH);
    cudaGetSymbolAddress((void**)&EA2, g_EA2);
    cudaGetSymbolAddress((void**)&S,   g_S);
    cudaGetSymbolAddress((void**)&XH,  g_XH);
    cudaGetSymbolAddress((void**)&X1,  g_X1);
    cudaGetSymbolAddress((void**)&SRC, g_SRC);
    cudaGetSymbolAddress((void**)&DST, g_DST);
    cudaGetSymbolAddress((void**)&WTH, g_WTH);
    cudaGetSymbolAddress((void**)&WTL, g_WTL);

    // weight offsets (k-units): e_w1_0@0(1088) e_w2_0@1088 n_wm_0@1344 n_w1_0@2112
    // n_w2_0@2880 e_w1_1@3136 e_w2_1@3904 p_w1@4160
    struct { const float* w; int K, Kpad; size_t off; } wts[8] = {
        { e_w1_0, 1030, 1088, 0    },
        { e_w2_0, 256,  256,  1088 },
        { n_wm_0, 768,  768,  1344 },
        { n_w1_0, 768,  768,  2112 },
        { n_w2_0, 256,  256,  2880 },
        { e_w1_1, 768,  768,  3136 },
        { e_w2_1, 256,  256,  3904 },
        { p_w1,   256,  256,  4160 },
    };
    for (int i = 0; i < 8; i++) {
        int total = 256 * wts[i].Kpad;
        wt_kernel<<<(total + 255) / 256, 256>>>(wts[i].w, wts[i].K, wts[i].Kpad,
                                                WTH + 256 * wts[i].off, WTL + 256 * wts[i].off);
    }

    detect_kernel<<<1, 256>>>(ei32);
    prep_kernel<<<2048, 256>>>(ei32);
    count_kernel<<<(NE + 255) / 256, 256>>>();

    // ---- Layer 0 edge model: EH = relu([x[src],x[dst],ea] @ e_w1_0 + b), K=1030
    run_tc(1, NE, 1030, 1088,
           x, SRC, 512, 512,  x, DST, 512, 512,  eattr, 6,
           WTH + 256 * 0, WTL + 256 * 0, e_b1_0, nullptr, EH);
    // EA = EH @ e_w2_0 + b
    run_tc(0, NE, 256, 256,
           EH, nullptr, 256, 256,  EH, nullptr, 0, 256,  EH, 256,
           WTH + 256 * 1088, WTL + 256 * 1088, e_b2_0, nullptr, EA);

    // ---- Layer 0 node model: EH = relu([x[src],EA] @ n_wm_0 + b), K=768
    run_tc(1, NE, 768, 768,
           x, SRC, 512, 512,  EA, nullptr, 256, 256,  EA, 256,
           WTH + 256 * 1344, WTL + 256 * 1344, n_bm_0, nullptr, EH);
    scatter_kernel<<<NE, 256>>>(EH);
    mean_kernel<<<NN, 256>>>();
    // XH = relu([x,S] @ n_w1_0 + b); X1 = XH @ n_w2_0 + b
    run_tc(1, NN, 768, 768,
           x, nullptr, 512, 512,  S, nullptr, 256, 256,  S, 256,
           WTH + 256 * 2112, WTL + 256 * 2112, n_b1_0, nullptr, XH);
    run_tc(0, NN, 256, 256,
           XH, nullptr, 256, 256,  XH, nullptr, 0, 256,  XH, 256,
           WTH + 256 * 2880, WTL + 256 * 2880, n_b2_0, nullptr, X1);

    // ---- Layer 1 edge model: EH = relu([X1[src],X1[dst],EA] @ e_w1_1 + b), K=768
    run_tc(1, NE, 768, 768,
           X1, SRC, 256, 256,  X1, DST, 256, 256,  EA, 256,
           WTH + 256 * 3136, WTL + 256 * 3136, e_b1_1, nullptr, EH);
    // EA2 = EH @ e_w2_1 + b + EA
    run_tc(2, NE, 256, 256,
           EH, nullptr, 256, 256,  EH, nullptr, 0, 256,  EH, 256,
           WTH + 256 * 3904, WTL + 256 * 3904, e_b2_1, EA, EA2);

    // ---- Edge predictor: EH = relu(EA2 @ p_w1 + b); out = EH @ p_w2 + b2
    run_tc(1, NE, 256, 256,
           EA2, nullptr, 256, 256,  EA2, nullptr, 0, 256,  EA2, 256,
           WTH + 256 * 4160, WTL + 256 * 4160, p_b1, nullptr, EH);
    pred_kernel<<<NE / 8, 256>>>(EH, p_w2, p_b2, out);

    (void)in_sizes; (void)n_in; (void)out_size;
}

// round 5
// speedup vs baseline: 2.6293x; 1.0074x over previous
#include <cuda_runtime.h>
#include <cuda_bf16.h>
#include <cstdint>
#include <cstddef>

#define NE 160000
#define NN 10000

typedef unsigned short u16;
typedef unsigned int u32;

// ---------------- scratch (device globals; bf16 stored as raw u16) ----------------
__device__ u16 g_XFh[(size_t)NN * 512], g_XFl[(size_t)NN * 512];   // x pre-split
__device__ u16 g_ETh[(size_t)NE * 32],  g_ETl[(size_t)NE * 32];    // edge_attr padded 6->32
__device__ u16 g_EAh[(size_t)NE * 256], g_EAl[(size_t)NE * 256];   // layer0 edge out
__device__ u16 g_EHh[(size_t)NE * 256], g_EHl[(size_t)NE * 256];   // hidden (reused)
__device__ u16 g_E2h[(size_t)NE * 256], g_E2l[(size_t)NE * 256];   // layer1 edge out
__device__ u16 g_Shh[NN * 256], g_Sll[NN * 256];                   // aggregated (split)
__device__ u16 g_XHh[NN * 256], g_XHl[NN * 256];
__device__ u16 g_X1h[NN * 256], g_X1l[NN * 256];
__device__ float g_F32[(size_t)NE * 256];                          // fp32 (msg / pred hidden)
__device__ float g_S[NN * 256];
__device__ float g_CNT[NN];
__device__ int   g_SRC[NE], g_DST[NE];
__device__ int   g_IS64;
__device__ u16 g_WTH[256 * 4416], g_WTL[256 * 4416];               // weights split/transposed

// ---------------- helpers ----------------
__device__ __forceinline__ u32 smem_u32(const void* p) {
    u32 a;
    asm("{ .reg .u64 t; cvta.to.shared.u64 t, %1; cvt.u32.u64 %0, t; }" : "=r"(a) : "l"(p));
    return a;
}
__device__ __forceinline__ void cp16(u32 dst, const void* src) {
    asm volatile("cp.async.ca.shared.global [%0], [%1], 16;" :: "r"(dst), "l"(src) : "memory");
}
__device__ __forceinline__ void ldsm4(u32* r, u32 addr) {
    asm volatile("ldmatrix.sync.aligned.m8n8.x4.shared.b16 {%0,%1,%2,%3}, [%4];"
                 : "=r"(r[0]), "=r"(r[1]), "=r"(r[2]), "=r"(r[3]) : "r"(addr));
}
__device__ __forceinline__ void mma_bf16(float* d, const u32* a, u32 b0, u32 b1) {
    asm volatile(
        "mma.sync.aligned.m16n8k16.row.col.f32.bf16.bf16.f32 "
        "{%0,%1,%2,%3}, {%4,%5,%6,%7}, {%8,%9}, {%0,%1,%2,%3};"
        : "+f"(d[0]), "+f"(d[1]), "+f"(d[2]), "+f"(d[3])
        : "r"(a[0]), "r"(a[1]), "r"(a[2]), "r"(a[3]), "r"(b0), "r"(b1));
}
__device__ __forceinline__ float up16(u16 u) { return __uint_as_float(((u32)u) << 16); }

// smem geometry: row stride 40 bf16 (80B) -> ldsm conflict-free
#define RSB   80
#define STAGE 61440   // Ah 10240 | Al 10240 | Bh 20480 | Bl 20480
#define SMEM_SZ (2 * STAGE)

// ---------------- small prep kernels ----------------
__global__ void wt_kernel(const float* __restrict__ W, int K, int Kpad,
                          u16* __restrict__ H, u16* __restrict__ L) {
    int idx = blockIdx.x * blockDim.x + threadIdx.x;
    if (idx >= 256 * Kpad) return;
    int n = idx / Kpad, k = idx - n * Kpad;
    float v = (k < K) ? W[(size_t)k * 256 + n] : 0.f;
    u32 b = __float_as_uint(v);
    H[idx] = (u16)(b >> 16);
    __nv_bfloat16 lo = __float2bfloat16_rn(v - __uint_as_float(b & 0xFFFF0000u));
    L[idx] = *(u16*)&lo;
}

__global__ void split_kernel(const float* __restrict__ src, int n,
                             u16* __restrict__ H, u16* __restrict__ L) {
    int i = blockIdx.x * blockDim.x + threadIdx.x;
    if (i >= n) return;
    float v = src[i];
    u32 b = __float_as_uint(v);
    H[i] = (u16)(b >> 16);
    __nv_bfloat16 lo = __float2bfloat16_rn(v - __uint_as_float(b & 0xFFFF0000u));
    L[i] = *(u16*)&lo;
}

__global__ void et_kernel(const float* __restrict__ ea) {
    int i = blockIdx.x * blockDim.x + threadIdx.x;
    if (i >= NE * 32) return;
    int e = i >> 5, k = i & 31;
    float v = (k < 6) ? ea[e * 6 + k] : 0.f;
    u32 b = __float_as_uint(v);
    g_ETh[i] = (u16)(b >> 16);
    __nv_bfloat16 lo = __float2bfloat16_rn(v - __uint_as_float(b & 0xFFFF0000u));
    g_ETl[i] = *(u16*)&lo;
}

__global__ void detect_kernel(const int* __restrict__ ei32) {
    __shared__ int any_nonzero;
    if (threadIdx.x == 0) any_nonzero = 0;
    __syncthreads();
    for (int i = threadIdx.x; i < 2048; i += blockDim.x) {
        int pos = 2 * (i * (NE / 2048)) + 1;
        if (ei32[pos] != 0) any_nonzero = 1;
    }
    __syncthreads();
    if (threadIdx.x == 0) g_IS64 = any_nonzero ? 0 : 1;
}

__global__ void prep_kernel(const int* __restrict__ ei32) {
    int i = blockIdx.x * blockDim.x + threadIdx.x;
    int stride = gridDim.x * blockDim.x;
    const int is64 = g_IS64;
    for (int j = i; j < NN * 256; j += stride) g_S[j] = 0.f;
    for (int j = i; j < NN; j += stride) g_CNT[j] = 0.f;
    for (int j = i; j < NE; j += stride) {
        int s, d;
        if (is64) { s = ei32[2 * j]; d = ei32[2 * (NE + j)]; }
        else      { s = ei32[j];     d = ei32[NE + j]; }
        g_SRC[j] = min(max(s, 0), NN - 1);
        g_DST[j] = min(max(d, 0), NN - 1);
    }
}

__global__ void count_kernel() {
    int e = blockIdx.x * blockDim.x + threadIdx.x;
    if (e < NE) atomicAdd(&g_CNT[g_DST[e]], 1.f);
}

// ---------------- HMMA gather-GEMM, pre-split bf16 operands ----------------
// C[M,256] = act(concat(A0[i0], A1[i1], A2[row]) @ W + b) (+Res)
// CTA 128x256, 8 warps of 64x64, K-chunk 32, cp.async 2-stage pipeline.
template<bool RELU, bool HAS_RES, bool OUT_SPLIT>
__global__ void __launch_bounds__(256, 1) gemm2(
    int M, int nch,
    const u16* __restrict__ A0h, const u16* __restrict__ A0l, const int* __restrict__ I0, int w0, int ld0,
    const u16* __restrict__ A1h, const u16* __restrict__ A1l, const int* __restrict__ I1, int ld1,
    const u16* __restrict__ A2h, const u16* __restrict__ A2l, int ld2, int w01,
    const u16* __restrict__ WtH, const u16* __restrict__ WtL, int Kpad,
    const float* __restrict__ bias,
    const u16* __restrict__ ResH, const u16* __restrict__ ResL,
    float* __restrict__ Cf, u16* __restrict__ Ch, u16* __restrict__ Cl)
{
    extern __shared__ __align__(128) char smem[];
    const u32 sb = smem_u32(smem);
    const int tid = threadIdx.x;
    const int lane = tid & 31, wid = tid >> 5;
    const int warp_m = wid & 1, warp_n = wid >> 1;
    const int bm = blockIdx.x * 128;

    // ---- per-thread A gather pointers (row = tid>>1) ----
    const int arow = tid >> 1, ahalf = tid & 1;
    const int gmc = min(bm + arow, M - 1);
    const int r0i = I0 ? I0[gmc] : gmc;
    const int r1i = I1 ? I1[gmc] : gmc;
    const u16* pa0h = A0h + (size_t)r0i * ld0;
    const u16* pa0l = A0l + (size_t)r0i * ld0;
    const u16* pa1h = A1h ? (A1h + (size_t)r1i * ld1) : nullptr;
    const u16* pa1l = A1l ? (A1l + (size_t)r1i * ld1) : nullptr;
    const u16* pa2h = A2h ? (A2h + (size_t)gmc * ld2) : nullptr;
    const u16* pa2l = A2l ? (A2l + (size_t)gmc * ld2) : nullptr;
    // B: thread owns output-col row tid
    const u16* pbh = WtH + (size_t)tid * Kpad;
    const u16* pbl = WtL + (size_t)tid * Kpad;

    float acc[4][8][4];
    #pragma unroll
    for (int a = 0; a < 4; a++)
        #pragma unroll
        for (int b = 0; b < 8; b++)
            #pragma unroll
            for (int c = 0; c < 4; c++) acc[a][b][c] = 0.f;

    // ---- prefetch lambda (macro-style) ----
    auto prefetch = [&](int c) {
        const int k0 = c << 5;
        const u32 st = sb + (c & 1) * STAGE;
        // A: row arow, this thread's 32B half (16 elems) of the 64B hi + 64B lo
        const u16 *sh, *sl;
        int kk;
        if (k0 < w0)        { sh = pa0h; sl = pa0l; kk = k0; }
        else if (k0 < w01)  { sh = pa1h; sl = pa1l; kk = k0 - w0; }
        else                { sh = pa2h; sl = pa2l; kk = k0 - w01; }
        u32 da = st + (u32)arow * RSB + ahalf * 32;
        cp16(da,              sh + kk + ahalf * 16);
        cp16(da + 16,         sh + kk + ahalf * 16 + 8);
        cp16(da + 10240,      sl + kk + ahalf * 16);
        cp16(da + 10240 + 16, sl + kk + ahalf * 16 + 8);
        // B: row tid, 64B hi + 64B lo
        u32 db = st + 20480 + (u32)tid * RSB;
        #pragma unroll
        for (int j = 0; j < 4; j++) {
            cp16(db + j * 16,         pbh + k0 + j * 8);
            cp16(db + 20480 + j * 16, pbl + k0 + j * 8);
        }
    };

    prefetch(0);
    asm volatile("cp.async.commit_group;" ::: "memory");

    for (int c = 0; c < nch; c++) {
        if (c + 1 < nch) {
            prefetch(c + 1);
            asm volatile("cp.async.commit_group;" ::: "memory");
            asm volatile("cp.async.wait_group 1;" ::: "memory");
        } else {
            asm volatile("cp.async.wait_group 0;" ::: "memory");
        }
        __syncthreads();

        const u32 st = sb + (c & 1) * STAGE;
        const u32 aH = st, aL = st + 10240, bH = st + 20480, bL = st + 40960;

        #pragma unroll
        for (int kk = 0; kk < 2; kk++) {
            u32 Afh[4][4], Afl[4][4];
            #pragma unroll
            for (int mf = 0; mf < 4; mf++) {
                u32 off = (u32)(warp_m * 64 + mf * 16 + (lane & 15)) * RSB
                        + kk * 32 + ((lane >> 4) << 4);
                ldsm4(Afh[mf], aH + off);
                ldsm4(Afl[mf], aL + off);
            }
            #pragma unroll
            for (int nf = 0; nf < 4; nf++) {
                u32 off = (u32)(warp_n * 64 + nf * 16 + ((lane >> 4) & 1) * 8 + (lane & 7)) * RSB
                        + kk * 32 + ((lane >> 3) & 1) * 16;
                u32 bh[4], bl[4];
                ldsm4(bh, bH + off);
                ldsm4(bl, bL + off);
                #pragma unroll
                for (int mf = 0; mf < 4; mf++) {
                    mma_bf16(acc[mf][2 * nf],     Afh[mf], bh[0], bh[1]);
                    mma_bf16(acc[mf][2 * nf + 1], Afh[mf], bh[2], bh[3]);
                }
                #pragma unroll
                for (int mf = 0; mf < 4; mf++) {
                    mma_bf16(acc[mf][2 * nf],     Afh[mf], bl[0], bl[1]);
                    mma_bf16(acc[mf][2 * nf + 1], Afh[mf], bl[2], bl[3]);
                }
                #pragma unroll
                for (int mf = 0; mf < 4; mf++) {
                    mma_bf16(acc[mf][2 * nf],     Afl[mf], bh[0], bh[1]);
                    mma_bf16(acc[mf][2 * nf + 1], Afl[mf], bh[2], bh[3]);
                }
            }
        }
        __syncthreads();
    }

    // ---- epilogue ----
    const int gid = lane >> 2, tig = lane & 3;
    #pragma unroll
    for (int mf = 0; mf < 4; mf++) {
        #pragma unroll
        for (int half = 0; half < 2; half++) {
            const int r = bm + warp_m * 64 + mf * 16 + half * 8 + gid;
            if (r < M) {
                #pragma unroll
                for (int nidx = 0; nidx < 8; nidx++) {
                    const int col = warp_n * 64 + nidx * 8 + tig * 2;
                    float o0 = acc[mf][nidx][half * 2 + 0] + bias[col];
                    float o1 = acc[mf][nidx][half * 2 + 1] + bias[col + 1];
                    if (RELU) { o0 = fmaxf(o0, 0.f); o1 = fmaxf(o1, 0.f); }
                    if (HAS_RES) {
                        ushort2 rh = *(const ushort2*)&ResH[(size_t)r * 256 + col];
                        ushort2 rl = *(const ushort2*)&ResL[(size_t)r * 256 + col];
                        o0 += up16(rh.x) + up16(rl.x);
                        o1 += up16(rh.y) + up16(rl.y);
                    }
                    if (OUT_SPLIT) {
                        u32 b0 = __float_as_uint(o0), b1 = __float_as_uint(o1);
                        u32 hp = (b1 & 0xFFFF0000u) | (b0 >> 16);
                        float l0 = o0 - __uint_as_float(b0 & 0xFFFF0000u);
                        float l1 = o1 - __uint_as_float(b1 & 0xFFFF0000u);
                        u32 lp;
                        asm("cvt.rn.bf16x2.f32 %0, %1, %2;" : "=r"(lp) : "f"(l1), "f"(l0));
                        *(u32*)&Ch[(size_t)r * 256 + col] = hp;
                        *(u32*)&Cl[(size_t)r * 256 + col] = lp;
                    } else {
                        *(float2*)&Cf[(size_t)r * 256 + col] = make_float2(o0, o1);
                    }
                }
            }
        }
    }
}

// ---------------- scatter / mean / predictor ----------------
__global__ void scatter_kernel(const float* __restrict__ MSG) {
    int e = blockIdx.x;
    int d = g_DST[e];
    int c = threadIdx.x;
    atomicAdd(&g_S[d * 256 + c], MSG[(size_t)e * 256 + c]);
}

__global__ void mean_kernel() {
    int n = blockIdx.x, c = threadIdx.x;
    float v = g_S[n * 256 + c] / fmaxf(g_CNT[n], 1.f);
    u32 b = __float_as_uint(v);
    g_Shh[n * 256 + c] = (u16)(b >> 16);
    __nv_bfloat16 lo = __float2bfloat16_rn(v - __uint_as_float(b & 0xFFFF0000u));
    g_Sll[n * 256 + c] = *(u16*)&lo;
}

__global__ void pred_kernel(const float* __restrict__ PH, const float* __restrict__ w2,
                            const float* __restrict__ b2, float* __restrict__ out) {
    int e = blockIdx.x * 8 + (threadIdx.x >> 5);
    int lane = threadIdx.x & 31;
    if (e >= NE) return;
    float s = 0.f;
    #pragma unroll
    for (int c = 0; c < 256; c += 32)
        s += PH[(size_t)e * 256 + c + lane] * w2[c + lane];
    #pragma unroll
    for (int o = 16; o; o >>= 1) s += __shfl_xor_sync(0xffffffffu, s, o);
    if (lane == 0) out[e] = s + b2[0];
}

// ---------------- host dispatch ----------------
struct GArgs {
    int M, nch;
    const u16 *A0h, *A0l; const int* I0; int w0, ld0;
    const u16 *A1h, *A1l; const int* I1; int ld1;
    const u16 *A2h, *A2l; int ld2, w01;
    const u16 *WtH, *WtL; int Kpad;
    const float* bias;
    const u16 *ResH, *ResL;
    float* Cf; u16 *Ch, *Cl;
};

static void run_g(int mode /*0: f32+relu, 1: split+relu, 2: split, 3: split+res*/, const GArgs& a) {
    dim3 grid((a.M + 127) / 128), blk(256);
    switch (mode) {
    case 0:
        gemm2<true, false, false><<<grid, blk, SMEM_SZ>>>(a.M, a.nch,
            a.A0h, a.A0l, a.I0, a.w0, a.ld0, a.A1h, a.A1l, a.I1, a.ld1,
            a.A2h, a.A2l, a.ld2, a.w01, a.WtH, a.WtL, a.Kpad, a.bias,
            a.ResH, a.ResL, a.Cf, a.Ch, a.Cl);
        break;
    case 1:
        gemm2<true, false, true><<<grid, blk, SMEM_SZ>>>(a.M, a.nch,
            a.A0h, a.A0l, a.I0, a.w0, a.ld0, a.A1h, a.A1l, a.I1, a.ld1,
            a.A2h, a.A2l, a.ld2, a.w01, a.WtH, a.WtL, a.Kpad, a.bias,
            a.ResH, a.ResL, a.Cf, a.Ch, a.Cl);
        break;
    case 2:
        gemm2<false, false, true><<<grid, blk, SMEM_SZ>>>(a.M, a.nch,
            a.A0h, a.A0l, a.I0, a.w0, a.ld0, a.A1h, a.A1l, a.I1, a.ld1,
            a.A2h, a.A2l, a.ld2, a.w01, a.WtH, a.WtL, a.Kpad, a.bias,
            a.ResH, a.ResL, a.Cf, a.Ch, a.Cl);
        break;
    default:
        gemm2<false, true, true><<<grid, blk, SMEM_SZ>>>(a.M, a.nch,
            a.A0h, a.A0l, a.I0, a.w0, a.ld0, a.A1h, a.A1l, a.I1, a.ld1,
            a.A2h, a.A2l, a.ld2, a.w01, a.WtH, a.WtL, a.Kpad, a.bias,
            a.ResH, a.ResL, a.Cf, a.Ch, a.Cl);
        break;
    }
}

extern "C" void kernel_launch(void* const* d_in, const int* in_sizes, int n_in,
                              void* d_out, int out_size)
{
    const float* x      = (const float*)d_in[0];
    const int*   ei32   = (const int*)d_in[1];
    const float* eattr  = (const float*)d_in[2];
    const float* e_w1_0 = (const float*)d_in[3];
    const float* e_b1_0 = (const float*)d_in[4];
    const float* e_w2_0 = (const float*)d_in[5];
    const float* e_b2_0 = (const float*)d_in[6];
    const float* n_wm_0 = (const float*)d_in[7];
    const float* n_bm_0 = (const float*)d_in[8];
    const float* n_w1_0 = (const float*)d_in[9];
    const float* n_b1_0 = (const float*)d_in[10];
    const float* n_w2_0 = (const float*)d_in[11];
    const float* n_b2_0 = (const float*)d_in[12];
    const float* e_w1_1 = (const float*)d_in[13];
    const float* e_b1_1 = (const float*)d_in[14];
    const float* e_w2_1 = (const float*)d_in[15];
    const float* e_b2_1 = (const float*)d_in[16];
    // d_in[17..22]: layer-1 node model — dead code for the output
    const float* p_w1   = (const float*)d_in[23];
    const float* p_b1   = (const float*)d_in[24];
    const float* p_w2   = (const float*)d_in[25];
    const float* p_b2   = (const float*)d_in[26];
    float* out = (float*)d_out;

#define SYM(T, v, s) T* v; cudaGetSymbolAddress((void**)&v, s)
    SYM(u16, XFh, g_XFh); SYM(u16, XFl, g_XFl);
    SYM(u16, ETh, g_ETh); SYM(u16, ETl, g_ETl);
    SYM(u16, EAh, g_EAh); SYM(u16, EAl, g_EAl);
    SYM(u16, EHh, g_EHh); SYM(u16, EHl, g_EHl);
    SYM(u16, E2h, g_E2h); SYM(u16, E2l, g_E2l);
    SYM(u16, Shh, g_Shh); SYM(u16, Sll, g_Sll);
    SYM(u16, XHh, g_XHh); SYM(u16, XHl, g_XHl);
    SYM(u16, X1h, g_X1h); SYM(u16, X1l, g_X1l);
    SYM(float, F32, g_F32);
    SYM(int, SRC, g_SRC); SYM(int, DST, g_DST);
    SYM(u16, WTH, g_WTH); SYM(u16, WTL, g_WTL);
#undef SYM

    cudaFuncSetAttribute(gemm2<true, false, false>, cudaFuncAttributeMaxDynamicSharedMemorySize, SMEM_SZ);
    cudaFuncSetAttribute(gemm2<true, false, true>,  cudaFuncAttributeMaxDynamicSharedMemorySize, SMEM_SZ);
    cudaFuncSetAttribute(gemm2<false, false, true>, cudaFuncAttributeMaxDynamicSharedMemorySize, SMEM_SZ);
    cudaFuncSetAttribute(gemm2<false, true, true>,  cudaFuncAttributeMaxDynamicSharedMemorySize, SMEM_SZ);

    // weight table: offsets in k-units
    struct { const float* w; int K, Kpad; size_t off; } wts[8] = {
        { e_w1_0, 1030, 1056, 0    },
        { e_w2_0, 256,  256,  1056 },
        { n_wm_0, 768,  768,  1312 },
        { n_w1_0, 768,  768,  2080 },
        { n_w2_0, 256,  256,  2848 },
        { e_w1_1, 768,  768,  3104 },
        { e_w2_1, 256,  256,  3872 },
        { p_w1,   256,  256,  4128 },
    };
    for (int i = 0; i < 8; i++) {
        int total = 256 * wts[i].Kpad;
        wt_kernel<<<(total + 255) / 256, 256>>>(wts[i].w, wts[i].K, wts[i].Kpad,
                                                WTH + 256 * wts[i].off, WTL + 256 * wts[i].off);
    }

    detect_kernel<<<1, 256>>>(ei32);
    prep_kernel<<<2048, 256>>>(ei32);
    count_kernel<<<(NE + 255) / 256, 256>>>();
    split_kernel<<<(NN * 512 + 255) / 256, 256>>>(x, NN * 512, XFh, XFl);
    et_kernel<<<(NE * 32 + 255) / 256, 256>>>(eattr);

    GArgs a{};

    // 1) EH = relu([x[src], x[dst], ea] @ e_w1_0 + b)   K=1056
    a = { NE, 1056 / 32, XFh, XFl, SRC, 512, 512, XFh, XFl, DST, 512,
          ETh, ETl, 32, 1024, WTH + 256 * 0, WTL + 256 * 0, 1056,
          e_b1_0, nullptr, nullptr, nullptr, EHh, EHl };
    run_g(1, a);
    // 2) EA = EH @ e_w2_0 + b
    a = { NE, 256 / 32, EHh, EHl, nullptr, 256, 256, nullptr, nullptr, nullptr, 256,
          nullptr, nullptr, 256, 256, WTH + 256 * 1056, WTL + 256 * 1056, 256,
          e_b2_0, nullptr, nullptr, nullptr, EAh, EAl };
    run_g(2, a);
    // 3) MSG = relu([x[src], EA] @ n_wm_0 + b)  -> fp32 (for scatter)
    a = { NE, 768 / 32, XFh, XFl, SRC, 512, 512, EAh, EAl, nullptr, 256,
          nullptr, nullptr, 256, 768, WTH + 256 * 1312, WTL + 256 * 1312, 768,
          n_bm_0, nullptr, nullptr, F32, nullptr, nullptr };
    run_g(0, a);
    scatter_kernel<<<NE, 256>>>(F32);
    mean_kernel<<<NN, 256>>>();
    // 4) XH = relu([x, S] @ n_w1_0 + b)
    a = { NN, 768 / 32, XFh, XFl, nullptr, 512, 512, Shh, Sll, nullptr, 256,
          nullptr, nullptr, 256, 768, WTH + 256 * 2080, WTL + 256 * 2080, 768,
          n_b1_0, nullptr, nullptr, nullptr, XHh, XHl };
    run_g(1, a);
    // 5) X1 = XH @ n_w2_0 + b
    a = { NN, 256 / 32, XHh, XHl, nullptr, 256, 256, nullptr, nullptr, nullptr, 256,
          nullptr, nullptr, 256, 256, WTH + 256 * 2848, WTL + 256 * 2848, 256,
          n_b2_0, nullptr, nullptr, nullptr, X1h, X1l };
    run_g(2, a);
    // 6) EH = relu([X1[src], X1[dst], EA] @ e_w1_1 + b)
    a = { NE, 768 / 32, X1h, X1l, SRC, 256, 256, X1h, X1l, DST, 256,
          EAh, EAl, 256, 512, WTH + 256 * 3104, WTL + 256 * 3104, 768,
          e_b1_1, nullptr, nullptr, nullptr, EHh, EHl };
    run_g(1, a);
    // 7) EA2 = EH @ e_w2_1 + b + EA
    a = { NE, 256 / 32, EHh, EHl, nullptr, 256, 256, nullptr, nullptr, nullptr, 256,
          nullptr, nullptr, 256, 256, WTH + 256 * 3872, WTL + 256 * 3872, 256,
          e_b2_1, EAh, EAl, nullptr, E2h, E2l };
    run_g(3, a);
    // 8) PH = relu(EA2 @ p_w1 + b) -> fp32
    a = { NE, 256 / 32, E2h, E2l, nullptr, 256, 256, nullptr, nullptr, nullptr, 256,
          nullptr, nullptr, 256, 256, WTH + 256 * 4128, WTL + 256 * 4128, 256,
          p_b1, nullptr, nullptr, F32, nullptr, nullptr };
    run_g(0, a);
    // 9) out = PH @ p_w2 + b2
    pred_kernel<<<NE / 8, 256>>>(F32, p_w2, p_b2, out);

    (void)in_sizes; (void)n_in; (void)out_size;
}

// round 6
// speedup vs baseline: 4.3419x; 1.6513x over previous
#include <cuda_runtime.h>
#include <cuda_bf16.h>
#include <cstdint>
#include <cstddef>

#define NE 160000
#define NN 10000

typedef unsigned short u16;
typedef unsigned int u32;

// ---------------- scratch (device globals) ----------------
__device__ u16 g_XFh[(size_t)NN * 512], g_XFl[(size_t)NN * 512];   // x pre-split
__device__ u16 g_EAh[(size_t)NE * 256], g_EAl[(size_t)NE * 256];   // layer0 edge out
__device__ u16 g_EHh[(size_t)NE * 256], g_EHl[(size_t)NE * 256];   // hidden (reused)
__device__ u16 g_E2h[(size_t)NE * 256], g_E2l[(size_t)NE * 256];   // layer1 edge out
__device__ u16 g_Shh[NN * 256], g_Sll[NN * 256];                   // aggregated (split)
__device__ u16 g_XHh[NN * 256], g_XHl[NN * 256];
__device__ u16 g_X1h[NN * 256], g_X1l[NN * 256];
__device__ float g_U[NN * 256], g_V[NN * 256], g_P[NN * 256];      // node-side partials
__device__ float g_F32[(size_t)NE * 256];                          // pred hidden
__device__ float g_S[NN * 256];
__device__ float g_CNT[NN];
__device__ int   g_SRC[NE], g_DST[NE];
__device__ int   g_IS64;
__device__ u16 g_WTH[256 * 4416], g_WTL[256 * 4416];               // weights split/transposed

// ---------------- helpers ----------------
__device__ __forceinline__ u32 smem_u32(const void* p) {
    u32 a;
    asm("{ .reg .u64 t; cvta.to.shared.u64 t, %1; cvt.u32.u64 %0, t; }" : "=r"(a) : "l"(p));
    return a;
}
__device__ __forceinline__ void cp16(u32 dst, const void* src) {
    asm volatile("cp.async.ca.shared.global [%0], [%1], 16;" :: "r"(dst), "l"(src) : "memory");
}
__device__ __forceinline__ void ldsm4(u32* r, u32 addr) {
    asm volatile("ldmatrix.sync.aligned.m8n8.x4.shared.b16 {%0,%1,%2,%3}, [%4];"
                 : "=r"(r[0]), "=r"(r[1]), "=r"(r[2]), "=r"(r[3]) : "r"(addr));
}
__device__ __forceinline__ void mma_bf16(float* d, const u32* a, u32 b0, u32 b1) {
    asm volatile(
        "mma.sync.aligned.m16n8k16.row.col.f32.bf16.bf16.f32 "
        "{%0,%1,%2,%3}, {%4,%5,%6,%7}, {%8,%9}, {%0,%1,%2,%3};"
        : "+f"(d[0]), "+f"(d[1]), "+f"(d[2]), "+f"(d[3])
        : "r"(a[0]), "r"(a[1]), "r"(a[2]), "r"(a[3]), "r"(b0), "r"(b1));
}
__device__ __forceinline__ float up16(u16 u) { return __uint_as_float(((u32)u) << 16); }

#define RSB   80
#define STAGE 61440   // Ah 10240 | Al 10240 | Bh 20480 | Bl 20480
#define SMEM_SZ (2 * STAGE)

// ---------------- small prep kernels ----------------
__global__ void wt_kernel(const float* __restrict__ W, int K, int Kpad,
                          u16* __restrict__ H, u16* __restrict__ L) {
    int idx = blockIdx.x * blockDim.x + threadIdx.x;
    if (idx >= 256 * Kpad) return;
    int n = idx / Kpad, k = idx - n * Kpad;
    float v = (k < K) ? W[(size_t)k * 256 + n] : 0.f;
    u32 b = __float_as_uint(v);
    H[idx] = (u16)(b >> 16);
    __nv_bfloat16 lo = __float2bfloat16_rn(v - __uint_as_float(b & 0xFFFF0000u));
    L[idx] = *(u16*)&lo;
}

__global__ void split_kernel(const float* __restrict__ src, int n,
                             u16* __restrict__ H, u16* __restrict__ L) {
    int i = blockIdx.x * blockDim.x + threadIdx.x;
    if (i >= n) return;
    float v = src[i];
    u32 b = __float_as_uint(v);
    H[i] = (u16)(b >> 16);
    __nv_bfloat16 lo = __float2bfloat16_rn(v - __uint_as_float(b & 0xFFFF0000u));
    L[i] = *(u16*)&lo;
}

__global__ void detect_kernel(const int* __restrict__ ei32) {
    __shared__ int any_nonzero;
    if (threadIdx.x == 0) any_nonzero = 0;
    __syncthreads();
    for (int i = threadIdx.x; i < 2048; i += blockDim.x) {
        int pos = 2 * (i * (NE / 2048)) + 1;
        if (ei32[pos] != 0) any_nonzero = 1;
    }
    __syncthreads();
    if (threadIdx.x == 0) g_IS64 = any_nonzero ? 0 : 1;
}

__global__ void prep_kernel(const int* __restrict__ ei32) {
    int i = blockIdx.x * blockDim.x + threadIdx.x;
    int stride = gridDim.x * blockDim.x;
    const int is64 = g_IS64;
    for (int j = i; j < NN * 256; j += stride) g_S[j] = 0.f;
    for (int j = i; j < NN; j += stride) g_CNT[j] = 0.f;
    for (int j = i; j < NE; j += stride) {
        int s, d;
        if (is64) { s = ei32[2 * j]; d = ei32[2 * (NE + j)]; }
        else      { s = ei32[j];     d = ei32[NE + j]; }
        g_SRC[j] = min(max(s, 0), NN - 1);
        g_DST[j] = min(max(d, 0), NN - 1);
    }
}

__global__ void count_kernel() {
    int e = blockIdx.x * blockDim.x + threadIdx.x;
    if (e < NE) atomicAdd(&g_CNT[g_DST[e]], 1.f);
}

// combine1: EH = relu(U[src] + V[dst] + ea @ W1c + b), split-stored
__global__ void combine1_kernel(const float* __restrict__ ea, const float* __restrict__ W1c,
                                const float* __restrict__ bias) {
    __shared__ float w[6 * 256];
    __shared__ float bb[256];
    int tid = threadIdx.x;
    for (int i = tid; i < 6 * 256; i += 256) w[i] = W1c[i];
    bb[tid] = bias[tid];
    __syncthreads();
    #pragma unroll 1
    for (int j = 0; j < 8; j++) {
        int e = blockIdx.x * 8 + j;
        int s = g_SRC[e], d = g_DST[e];
        float ev[6];
        #pragma unroll
        for (int k = 0; k < 6; k++) ev[k] = ea[e * 6 + k];
        float v = g_U[s * 256 + tid] + g_V[d * 256 + tid] + bb[tid];
        #pragma unroll
        for (int k = 0; k < 6; k++) v += ev[k] * w[k * 256 + tid];
        v = fmaxf(v, 0.f);
        u32 b = __float_as_uint(v);
        g_EHh[(size_t)e * 256 + tid] = (u16)(b >> 16);
        __nv_bfloat16 lo = __float2bfloat16_rn(v - __uint_as_float(b & 0xFFFF0000u));
        g_EHl[(size_t)e * 256 + tid] = *(u16*)&lo;
    }
}

__global__ void mean_kernel() {
    int n = blockIdx.x, c = threadIdx.x;
    float v = g_S[n * 256 + c] / fmaxf(g_CNT[n], 1.f);
    u32 b = __float_as_uint(v);
    g_Shh[n * 256 + c] = (u16)(b >> 16);
    __nv_bfloat16 lo = __float2bfloat16_rn(v - __uint_as_float(b & 0xFFFF0000u));
    g_Sll[n * 256 + c] = *(u16*)&lo;
}

__global__ void pred_kernel(const float* __restrict__ PH, const float* __restrict__ w2,
                            const float* __restrict__ b2, float* __restrict__ out) {
    int e = blockIdx.x * 8 + (threadIdx.x >> 5);
    int lane = threadIdx.x & 31;
    if (e >= NE) return;
    float s = 0.f;
    #pragma unroll
    for (int c = 0; c < 256; c += 32)
        s += PH[(size_t)e * 256 + c + lane] * w2[c + lane];
    #pragma unroll
    for (int o = 16; o; o >>= 1) s += __shfl_xor_sync(0xffffffffu, s, o);
    if (lane == 0) out[e] = s + b2[0];
}

// ---------------- HMMA gather-GEMM ----------------
// C[M,256] = epi(concat(A0[i0], A1[i1]) @ W + b)
// Epilogue options: RELU; RES (split residual); SPLIT out vs f32 out;
// ADD (+= G1[IG1[r]] (+ G2[IG2[r]])); SCAT (atomicAdd into Cf[SDST[r]]).
template<bool RELU, bool RES, bool SPLIT, bool ADD, bool SCAT>
__global__ void __launch_bounds__(256, 1) gemm2(
    int M, int nch,
    const u16* __restrict__ A0h, const u16* __restrict__ A0l, const int* __restrict__ I0, int w0, int ld0,
    const u16* __restrict__ A1h, const u16* __restrict__ A1l, const int* __restrict__ I1, int ld1,
    const u16* __restrict__ WtH, const u16* __restrict__ WtL, int Kpad,
    const float* __restrict__ bias,
    const u16* __restrict__ ResH, const u16* __restrict__ ResL,
    const float* __restrict__ G1, const int* __restrict__ IG1,
    const float* __restrict__ G2, const int* __restrict__ IG2,
    const int* __restrict__ SDST,
    float* __restrict__ Cf, u16* __restrict__ Ch, u16* __restrict__ Cl)
{
    extern __shared__ __align__(128) char smem[];
    const u32 sb = smem_u32(smem);
    const int tid = threadIdx.x;
    const int lane = tid & 31, wid = tid >> 5;
    const int warp_m = wid & 1, warp_n = wid >> 1;
    const int bm = blockIdx.x * 128;

    const int arow = tid >> 1, ahalf = tid & 1;
    const int gmc = min(bm + arow, M - 1);
    const int r0i = I0 ? I0[gmc] : gmc;
    const int r1i = I1 ? I1[gmc] : gmc;
    const u16* pa0h = A0h + (size_t)r0i * ld0;
    const u16* pa0l = A0l + (size_t)r0i * ld0;
    const u16* pa1h = A1h ? (A1h + (size_t)r1i * ld1) : nullptr;
    const u16* pa1l = A1l ? (A1l + (size_t)r1i * ld1) : nullptr;
    const u16* pbh = WtH + (size_t)tid * Kpad;
    const u16* pbl = WtL + (size_t)tid * Kpad;

    float acc[4][8][4];
    #pragma unroll
    for (int a = 0; a < 4; a++)
        #pragma unroll
        for (int b = 0; b < 8; b++)
            #pragma unroll
            for (int c = 0; c < 4; c++) acc[a][b][c] = 0.f;

    auto prefetch = [&](int c) {
        const int k0 = c << 5;
        const u32 st = sb + (c & 1) * STAGE;
        const u16 *sh, *sl;
        int kk;
        if (k0 < w0) { sh = pa0h; sl = pa0l; kk = k0; }
        else         { sh = pa1h; sl = pa1l; kk = k0 - w0; }
        u32 da = st + (u32)arow * RSB + ahalf * 32;
        cp16(da,              sh + kk + ahalf * 16);
        cp16(da + 16,         sh + kk + ahalf * 16 + 8);
        cp16(da + 10240,      sl + kk + ahalf * 16);
        cp16(da + 10240 + 16, sl + kk + ahalf * 16 + 8);
        u32 db = st + 20480 + (u32)tid * RSB;
        #pragma unroll
        for (int j = 0; j < 4; j++) {
            cp16(db + j * 16,         pbh + k0 + j * 8);
            cp16(db + 20480 + j * 16, pbl + k0 + j * 8);
        }
    };

    prefetch(0);
    asm volatile("cp.async.commit_group;" ::: "memory");

    for (int c = 0; c < nch; c++) {
        if (c + 1 < nch) {
            prefetch(c + 1);
            asm volatile("cp.async.commit_group;" ::: "memory");
            asm volatile("cp.async.wait_group 1;" ::: "memory");
        } else {
            asm volatile("cp.async.wait_group 0;" ::: "memory");
        }
        __syncthreads();

        const u32 st = sb + (c & 1) * STAGE;
        const u32 aH = st, aL = st + 10240, bH = st + 20480, bL = st + 40960;

        #pragma unroll
        for (int kk = 0; kk < 2; kk++) {
            u32 Afh[4][4], Afl[4][4];
            #pragma unroll
            for (int mf = 0; mf < 4; mf++) {
                u32 off = (u32)(warp_m * 64 + mf * 16 + (lane & 15)) * RSB
                        + kk * 32 + ((lane >> 4) << 4);
                ldsm4(Afh[mf], aH + off);
                ldsm4(Afl[mf], aL + off);
            }
            #pragma unroll
            for (int nf = 0; nf < 4; nf++) {
                u32 off = (u32)(warp_n * 64 + nf * 16 + ((lane >> 4) & 1) * 8 + (lane & 7)) * RSB
                        + kk * 32 + ((lane >> 3) & 1) * 16;
                u32 bh[4], bl[4];
                ldsm4(bh, bH + off);
                ldsm4(bl, bL + off);
                #pragma unroll
                for (int mf = 0; mf < 4; mf++) {
                    mma_bf16(acc[mf][2 * nf],     Afh[mf], bh[0], bh[1]);
                    mma_bf16(acc[mf][2 * nf + 1], Afh[mf], bh[2], bh[3]);
                }
                #pragma unroll
                for (int mf = 0; mf < 4; mf++) {
                    mma_bf16(acc[mf][2 * nf],     Afh[mf], bl[0], bl[1]);
                    mma_bf16(acc[mf][2 * nf + 1], Afh[mf], bl[2], bl[3]);
                }
                #pragma unroll
                for (int mf = 0; mf < 4; mf++) {
                    mma_bf16(acc[mf][2 * nf],     Afl[mf], bh[0], bh[1]);
                    mma_bf16(acc[mf][2 * nf + 1], Afl[mf], bh[2], bh[3]);
                }
            }
        }
        __syncthreads();
    }

    // ---- epilogue ----
    const int gid = lane >> 2, tig = lane & 3;
    #pragma unroll
    for (int mf = 0; mf < 4; mf++) {
        #pragma unroll
        for (int half = 0; half < 2; half++) {
            const int r = bm + warp_m * 64 + mf * 16 + half * 8 + gid;
            if (r < M) {
                const float* ag1 = nullptr;
                const float* ag2 = nullptr;
                int sd = 0;
                if (ADD) {
                    ag1 = G1 + (size_t)(IG1 ? IG1[r] : r) * 256;
                    if (G2) ag2 = G2 + (size_t)(IG2 ? IG2[r] : r) * 256;
                }
                if (SCAT) sd = SDST[r];
                #pragma unroll
                for (int nidx = 0; nidx < 8; nidx++) {
                    const int col = warp_n * 64 + nidx * 8 + tig * 2;
                    float o0 = acc[mf][nidx][half * 2 + 0];
                    float o1 = acc[mf][nidx][half * 2 + 1];
                    if (bias) { o0 += bias[col]; o1 += bias[col + 1]; }
                    if (ADD) {
                        o0 += ag1[col]; o1 += ag1[col + 1];
                        if (ag2) { o0 += ag2[col]; o1 += ag2[col + 1]; }
                    }
                    if (RELU) { o0 = fmaxf(o0, 0.f); o1 = fmaxf(o1, 0.f); }
                    if (RES) {
                        ushort2 rh = *(const ushort2*)&ResH[(size_t)r * 256 + col];
                        ushort2 rl = *(const ushort2*)&ResL[(size_t)r * 256 + col];
                        o0 += up16(rh.x) + up16(rl.x);
                        o1 += up16(rh.y) + up16(rl.y);
                    }
                    if (SCAT) {
                        atomicAdd(&Cf[(size_t)sd * 256 + col],     o0);
                        atomicAdd(&Cf[(size_t)sd * 256 + col + 1], o1);
                    } else if (SPLIT) {
                        u32 b0 = __float_as_uint(o0), b1 = __float_as_uint(o1);
                        u32 hp = (b1 & 0xFFFF0000u) | (b0 >> 16);
                        float l0 = o0 - __uint_as_float(b0 & 0xFFFF0000u);
                        float l1 = o1 - __uint_as_float(b1 & 0xFFFF0000u);
                        u32 lp;
                        asm("cvt.rn.bf16x2.f32 %0, %1, %2;" : "=r"(lp) : "f"(l1), "f"(l0));
                        *(u32*)&Ch[(size_t)r * 256 + col] = hp;
                        *(u32*)&Cl[(size_t)r * 256 + col] = lp;
                    } else {
                        *(float2*)&Cf[(size_t)r * 256 + col] = make_float2(o0, o1);
                    }
                }
            }
        }
    }
}

// ---------------- host dispatch ----------------
struct GArgs {
    int M, nch;
    const u16 *A0h, *A0l; const int* I0; int w0, ld0;
    const u16 *A1h, *A1l; const int* I1; int ld1;
    const u16 *WtH, *WtL; int Kpad;
    const float* bias;
    const u16 *ResH, *ResL;
    const float* G1; const int* IG1;
    const float* G2; const int* IG2;
    const int* SDST;
    float* Cf; u16 *Ch, *Cl;
};

#define LAUNCH(R, S, P, A, T) \
    gemm2<R, S, P, A, T><<<grid, blk, SMEM_SZ>>>(a.M, a.nch, \
        a.A0h, a.A0l, a.I0, a.w0, a.ld0, a.A1h, a.A1l, a.I1, a.ld1, \
        a.WtH, a.WtL, a.Kpad, a.bias, a.ResH, a.ResL, \
        a.G1, a.IG1, a.G2, a.IG2, a.SDST, a.Cf, a.Ch, a.Cl)

static void run_g(int mode, const GArgs& a) {
    dim3 grid((a.M + 127) / 128), blk(256);
    switch (mode) {
    case 0: LAUNCH(false, false, false, false, false); break; // f32 plain   (U,V,P,U1,V1)
    case 1: LAUNCH(true,  false, true,  false, false); break; // relu split  (GEMM4)
    case 2: LAUNCH(false, false, true,  false, false); break; // split       (GEMM2, GEMM5)
    case 3: LAUNCH(true,  false, false, true,  true ); break; // relu+add+scatter (MSG)
    case 4: LAUNCH(true,  false, true,  true,  false); break; // relu+add2 split  (layer1 edge)
    case 5: LAUNCH(false, true,  true,  false, false); break; // res split   (GEMM7)
    case 6: LAUNCH(true,  false, false, false, false); break; // relu f32    (GEMM8)
    }
}

extern "C" void kernel_launch(void* const* d_in, const int* in_sizes, int n_in,
                              void* d_out, int out_size)
{
    const float* x      = (const float*)d_in[0];
    const int*   ei32   = (const int*)d_in[1];
    const float* eattr  = (const float*)d_in[2];
    const float* e_w1_0 = (const float*)d_in[3];
    const float* e_b1_0 = (const float*)d_in[4];
    const float* e_w2_0 = (const float*)d_in[5];
    const float* e_b2_0 = (const float*)d_in[6];
    const float* n_wm_0 = (const float*)d_in[7];
    const float* n_bm_0 = (const float*)d_in[8];
    const float* n_w1_0 = (const float*)d_in[9];
    const float* n_b1_0 = (const float*)d_in[10];
    const float* n_w2_0 = (const float*)d_in[11];
    const float* n_b2_0 = (const float*)d_in[12];
    const float* e_w1_1 = (const float*)d_in[13];
    const float* e_b1_1 = (const float*)d_in[14];
    const float* e_w2_1 = (const float*)d_in[15];
    const float* e_b2_1 = (const float*)d_in[16];
    // d_in[17..22]: layer-1 node model — dead code for the output
    const float* p_w1   = (const float*)d_in[23];
    const float* p_b1   = (const float*)d_in[24];
    const float* p_w2   = (const float*)d_in[25];
    const float* p_b2   = (const float*)d_in[26];
    float* out = (float*)d_out;

#define SYM(T, v, s) T* v; cudaGetSymbolAddress((void**)&v, s)
    SYM(u16, XFh, g_XFh); SYM(u16, XFl, g_XFl);
    SYM(u16, EAh, g_EAh); SYM(u16, EAl, g_EAl);
    SYM(u16, EHh, g_EHh); SYM(u16, EHl, g_EHl);
    SYM(u16, E2h, g_E2h); SYM(u16, E2l, g_E2l);
    SYM(u16, Shh, g_Shh); SYM(u16, Sll, g_Sll);
    SYM(u16, XHh, g_XHh); SYM(u16, XHl, g_XHl);
    SYM(u16, X1h, g_X1h); SYM(u16, X1l, g_X1l);
    SYM(float, U, g_U); SYM(float, V, g_V); SYM(float, P, g_P);
    SYM(float, F32, g_F32); SYM(float, S, g_S);
    SYM(int, SRC, g_SRC); SYM(int, DST, g_DST);
    SYM(u16, WTH, g_WTH); SYM(u16, WTL, g_WTL);
#undef SYM

    cudaFuncSetAttribute(gemm2<false, false, false, false, false>, cudaFuncAttributeMaxDynamicSharedMemorySize, SMEM_SZ);
    cudaFuncSetAttribute(gemm2<true,  false, true,  false, false>, cudaFuncAttributeMaxDynamicSharedMemorySize, SMEM_SZ);
    cudaFuncSetAttribute(gemm2<false, false, true,  false, false>, cudaFuncAttributeMaxDynamicSharedMemorySize, SMEM_SZ);
    cudaFuncSetAttribute(gemm2<true,  false, false, true,  true >, cudaFuncAttributeMaxDynamicSharedMemorySize, SMEM_SZ);
    cudaFuncSetAttribute(gemm2<true,  false, true,  true,  false>, cudaFuncAttributeMaxDynamicSharedMemorySize, SMEM_SZ);
    cudaFuncSetAttribute(gemm2<false, true,  true,  false, false>, cudaFuncAttributeMaxDynamicSharedMemorySize, SMEM_SZ);
    cudaFuncSetAttribute(gemm2<true,  false, false, false, false>, cudaFuncAttributeMaxDynamicSharedMemorySize, SMEM_SZ);

    // weight split table (offsets in k-units within g_WTH/g_WTL)
    struct { const float* w; int K; size_t off; } wts[12] = {
        { e_w1_0,             512, 0    },   // W1a
        { e_w1_0 + 512 * 256, 512, 512  },   // W1b
        { e_w2_0,             256, 1024 },
        { n_wm_0,             512, 1280 },   // Wm_a
        { n_wm_0 + 512 * 256, 256, 1792 },   // Wm_b
        { n_w1_0,             768, 2048 },
        { n_w2_0,             256, 2816 },
        { e_w1_1,             256, 3072 },   // W11a
        { e_w1_1 + 256 * 256, 256, 3328 },   // W11b
        { e_w1_1 + 512 * 256, 256, 3584 },   // W11c
        { e_w2_1,             256, 3840 },
        { p_w1,               256, 4096 },
    };
    for (int i = 0; i < 12; i++) {
        int total = 256 * wts[i].K;
        wt_kernel<<<(total + 255) / 256, 256>>>(wts[i].w, wts[i].K, wts[i].K,
                                                WTH + 256 * wts[i].off, WTL + 256 * wts[i].off);
    }

    detect_kernel<<<1, 256>>>(ei32);
    prep_kernel<<<2048, 256>>>(ei32);
    count_kernel<<<(NE + 255) / 256, 256>>>();
    split_kernel<<<(NN * 512 + 255) / 256, 256>>>(x, NN * 512, XFh, XFl);

    GArgs a{};

    // U = x @ W1a, V = x @ W1b   (node GEMMs, fp32 out, no bias)
    a = { NN, 512 / 32, XFh, XFl, nullptr, 512, 512, nullptr, nullptr, nullptr, 512,
          WTH + 256 * 0, WTL + 256 * 0, 512, nullptr, nullptr, nullptr,
          nullptr, nullptr, nullptr, nullptr, nullptr, U, nullptr, nullptr };
    run_g(0, a);
    a.WtH = WTH + 256 * 512; a.WtL = WTL + 256 * 512; a.Cf = V;
    run_g(0, a);
    // EH = relu(U[src] + V[dst] + ea @ W1c + e_b1_0)  (combine, split out)
    combine1_kernel<<<NE / 8, 256>>>(eattr, e_w1_0 + 1024 * 256, e_b1_0);
    // EA = EH @ e_w2_0 + b  (split out)
    a = { NE, 256 / 32, EHh, EHl, nullptr, 256, 256, nullptr, nullptr, nullptr, 256,
          WTH + 256 * 1024, WTL + 256 * 1024, 256, e_b2_0, nullptr, nullptr,
          nullptr, nullptr, nullptr, nullptr, nullptr, nullptr, EAh, EAl };
    run_g(2, a);
    // P = x @ Wm_a  (fp32, no bias)
    a = { NN, 512 / 32, XFh, XFl, nullptr, 512, 512, nullptr, nullptr, nullptr, 512,
          WTH + 256 * 1280, WTL + 256 * 1280, 512, nullptr, nullptr, nullptr,
          nullptr, nullptr, nullptr, nullptr, nullptr, P, nullptr, nullptr };
    run_g(0, a);
    // MSG = relu(EA @ Wm_b + P[src] + n_bm_0)  scattered into S[dst]
    a = { NE, 256 / 32, EAh, EAl, nullptr, 256, 256, nullptr, nullptr, nullptr, 256,
          WTH + 256 * 1792, WTL + 256 * 1792, 256, n_bm_0, nullptr, nullptr,
          P, SRC, nullptr, nullptr, DST, S, nullptr, nullptr };
    run_g(3, a);
    mean_kernel<<<NN, 256>>>();
    // XH = relu([x, S] @ n_w1_0 + b)  (split)
    a = { NN, 768 / 32, XFh, XFl, nullptr, 512, 512, Shh, Sll, nullptr, 256,
          WTH + 256 * 2048, WTL + 256 * 2048, 768, n_b1_0, nullptr, nullptr,
          nullptr, nullptr, nullptr, nullptr, nullptr, nullptr, XHh, XHl };
    run_g(1, a);
    // X1 = XH @ n_w2_0 + b  (split)
    a = { NN, 256 / 32, XHh, XHl, nullptr, 256, 256, nullptr, nullptr, nullptr, 256,
          WTH + 256 * 2816, WTL + 256 * 2816, 256, n_b2_0, nullptr, nullptr,
          nullptr, nullptr, nullptr, nullptr, nullptr, nullptr, X1h, X1l };
    run_g(2, a);
    // U1 = X1 @ W11a, V1 = X1 @ W11b  (fp32, reuse U/V)
    a = { NN, 256 / 32, X1h, X1l, nullptr, 256, 256, nullptr, nullptr, nullptr, 256,
          WTH + 256 * 3072, WTL + 256 * 3072, 256, nullptr, nullptr, nullptr,
          nullptr, nullptr, nullptr, nullptr, nullptr, U, nullptr, nullptr };
    run_g(0, a);
    a.WtH = WTH + 256 * 3328; a.WtL = WTL + 256 * 3328; a.Cf = V;
    run_g(0, a);
    // EH2 = relu(EA @ W11c + U1[src] + V1[dst] + e_b1_1)  (split)
    a = { NE, 256 / 32, EAh, EAl, nullptr, 256, 256, nullptr, nullptr, nullptr, 256,
          WTH + 256 * 3584, WTL + 256 * 3584, 256, e_b1_1, nullptr, nullptr,
          U, SRC, V, DST, nullptr, nullptr, EHh, EHl };
    run_g(4, a);
    // EA2 = EH2 @ e_w2_1 + b + EA  (residual, split)
    a = { NE, 256 / 32, EHh, EHl, nullptr, 256, 256, nullptr, nullptr, nullptr, 256,
          WTH + 256 * 3840, WTL + 256 * 3840, 256, e_b2_1, EAh, EAl,
          nullptr, nullptr, nullptr, nullptr, nullptr, nullptr, E2h, E2l };
    run_g(5, a);
    // PH = relu(EA2 @ p_w1 + b)  (fp32)
    a = { NE, 256 / 32, E2h, E2l, nullptr, 256, 256, nullptr, nullptr, nullptr, 256,
          WTH + 256 * 4096, WTL + 256 * 4096, 256, p_b1, nullptr, nullptr,
          nullptr, nullptr, nullptr, nullptr, nullptr, F32, nullptr, nullptr };
    run_g(6, a);
    // out = PH @ p_w2 + b2
    pred_kernel<<<NE / 8, 256>>>(F32, p_w2, p_b2, out);

    (void)in_sizes; (void)n_in; (void)out_size;
}

// round 7
// speedup vs baseline: 4.3980x; 1.0129x over previous
#include <cuda_runtime.h>
#include <cuda_bf16.h>
#include <cstdint>
#include <cstddef>

#define NE 160000
#define NN 10000
typedef unsigned short u16;
typedef unsigned int u32;

// ---------------- scratch (device globals) ----------------
__device__ u16 g_XFh[(size_t)NN * 512], g_XFl[(size_t)NN * 512];
__device__ u16 g_EAh[(size_t)NE * 256], g_EAl[(size_t)NE * 256];
__device__ u16 g_EHh[(size_t)NE * 256], g_EHl[(size_t)NE * 256];
__device__ u16 g_E2h[(size_t)NE * 256], g_E2l[(size_t)NE * 256];
__device__ u16 g_Shh[NN * 256], g_Sll[NN * 256];
__device__ u16 g_XHh[NN * 256], g_XHl[NN * 256];
__device__ u16 g_X1h[NN * 256], g_X1l[NN * 256];
__device__ float g_U[NN * 256], g_V[NN * 256], g_P[NN * 256];
__device__ float g_S[NN * 256];
__device__ float g_CNT[NN];
__device__ int   g_SRC[NE], g_DST[NE];
__device__ int   g_IS64;
__device__ u16 g_WTH[256 * 4416], g_WTL[256 * 4416];

// ---------------- helpers ----------------
__device__ __forceinline__ u32 smem_u32(const void* p) {
    u32 a;
    asm("{ .reg .u64 t; cvta.to.shared.u64 t, %1; cvt.u32.u64 %0, t; }" : "=r"(a) : "l"(p));
    return a;
}
__device__ __forceinline__ void cp16(u32 dst, const void* src) {
    asm volatile("cp.async.ca.shared.global [%0], [%1], 16;" :: "r"(dst), "l"(src) : "memory");
}
__device__ __forceinline__ void ldsm4(u32* r, u32 addr) {
    asm volatile("ldmatrix.sync.aligned.m8n8.x4.shared.b16 {%0,%1,%2,%3}, [%4];"
                 : "=r"(r[0]), "=r"(r[1]), "=r"(r[2]), "=r"(r[3]) : "r"(addr));
}
__device__ __forceinline__ void mma_bf16(float* d, const u32* a, u32 b0, u32 b1) {
    asm volatile(
        "mma.sync.aligned.m16n8k16.row.col.f32.bf16.bf16.f32 "
        "{%0,%1,%2,%3}, {%4,%5,%6,%7}, {%8,%9}, {%0,%1,%2,%3};"
        : "+f"(d[0]), "+f"(d[1]), "+f"(d[2]), "+f"(d[3])
        : "r"(a[0]), "r"(a[1]), "r"(a[2]), "r"(a[3]), "r"(b0), "r"(b1));
}
__device__ __forceinline__ float up16(u16 u) { return __uint_as_float(((u32)u) << 16); }
__device__ __forceinline__ void sts128(u32 addr, u32 a, u32 b, u32 c, u32 d) {
    asm volatile("st.shared.v4.b32 [%0], {%1,%2,%3,%4};" :: "r"(addr), "r"(a), "r"(b), "r"(c), "r"(d) : "memory");
}
__device__ __forceinline__ void split2(float o0, float o1, u32& hp, u32& lp) {
    u32 b0 = __float_as_uint(o0), b1 = __float_as_uint(o1);
    hp = (b1 & 0xFFFF0000u) | (b0 >> 16);
    float l0 = o0 - __uint_as_float(b0 & 0xFFFF0000u);
    float l1 = o1 - __uint_as_float(b1 & 0xFFFF0000u);
    asm("cvt.rn.bf16x2.f32 %0, %1, %2;" : "=r"(lp) : "f"(l1), "f"(l0));
}

#define RSB   80
#define STAGE 61440    // Ah 10240 | Al 10240 | Bh 20480 | Bl 20480
#define EXTRA 11264    // COMB: w1ct 8192 + ea 3072 ; PRED: w2 1024
#define SMEM_SZ (2 * STAGE + EXTRA)

// ---------------- batched weight split/transpose ----------------
struct WtEnt { const float* w; int K; int off; };
struct WtJobs { WtEnt e[12]; };

__global__ void wt_all(WtJobs ja) {
    const WtEnt en = ja.e[blockIdx.y];
    int idx = blockIdx.x * blockDim.x + threadIdx.x;
    if (idx >= 256 * en.K) return;
    int n = idx / en.K, k = idx - n * en.K;
    float v = en.w[(size_t)k * 256 + n];
    u32 b = __float_as_uint(v);
    size_t o = (size_t)256 * en.off + idx;
    g_WTH[o] = (u16)(b >> 16);
    __nv_bfloat16 lo = __float2bfloat16_rn(v - __uint_as_float(b & 0xFFFF0000u));
    g_WTL[o] = *(u16*)&lo;
}

__global__ void split_kernel(const float* __restrict__ src, int n,
                             u16* __restrict__ H, u16* __restrict__ L) {
    int i = blockIdx.x * blockDim.x + threadIdx.x;
    if (i >= n) return;
    float v = src[i];
    u32 b = __float_as_uint(v);
    H[i] = (u16)(b >> 16);
    __nv_bfloat16 lo = __float2bfloat16_rn(v - __uint_as_float(b & 0xFFFF0000u));
    L[i] = *(u16*)&lo;
}

__global__ void detect_kernel(const int* __restrict__ ei32) {
    __shared__ int any_nonzero;
    if (threadIdx.x == 0) any_nonzero = 0;
    __syncthreads();
    for (int i = threadIdx.x; i < 2048; i += blockDim.x) {
        int pos = 2 * (i * (NE / 2048)) + 1;
        if (ei32[pos] != 0) any_nonzero = 1;
    }
    __syncthreads();
    if (threadIdx.x == 0) g_IS64 = any_nonzero ? 0 : 1;
}

__global__ void prep_kernel(const int* __restrict__ ei32, float* __restrict__ outp,
                            const float* __restrict__ b2) {
    int i = blockIdx.x * blockDim.x + threadIdx.x;
    int stride = gridDim.x * blockDim.x;
    const int is64 = g_IS64;
    const float bv = b2[0];
    for (int j = i; j < NN * 256; j += stride) g_S[j] = 0.f;
    for (int j = i; j < NN; j += stride) g_CNT[j] = 0.f;
    for (int j = i; j < NE; j += stride) {
        int s, d;
        if (is64) { s = ei32[2 * j]; d = ei32[2 * (NE + j)]; }
        else      { s = ei32[j];     d = ei32[NE + j]; }
        g_SRC[j] = min(max(s, 0), NN - 1);
        g_DST[j] = min(max(d, 0), NN - 1);
        outp[j] = bv;
    }
}

__global__ void count_kernel() {
    int e = blockIdx.x * blockDim.x + threadIdx.x;
    if (e < NE) atomicAdd(&g_CNT[g_DST[e]], 1.f);
}

__global__ void mean_kernel() {
    int n = blockIdx.x, c = threadIdx.x;
    float v = g_S[n * 256 + c] / fmaxf(g_CNT[n], 1.f);
    u32 b = __float_as_uint(v);
    g_Shh[n * 256 + c] = (u16)(b >> 16);
    __nv_bfloat16 lo = __float2bfloat16_rn(v - __uint_as_float(b & 0xFFFF0000u));
    g_Sll[n * 256 + c] = *(u16*)&lo;
}

// ---------------- unified HMMA GEMM ----------------
struct GP {
    int M, nch, Kpad;
    const u16 *A0h, *A0l; const int* I0; int w0, ld0;
    const u16 *A1h, *A1l; const int* I1; int ld1;
    const u16 *WtH, *WtL;
    const float* bias;
    const u16 *ResH, *ResL;
    const float* G1; const int* IG1;
    const float* G2; const int* IG2;
    const int* SDST;
    float* Cf; u16 *Ch, *Cl;
    // COMB
    const float *Uf, *Vf, *EAT, *W1c, *B1;
    // PRED
    const float* PW2; float* OutP;
    // multi-job
    const u16* jwh[3]; const u16* jwl[3]; float* jcf[3]; int njobs;
};

template<bool RELU, bool RES, bool SPLIT, bool ADD, bool SCAT, bool COMB, bool PRED>
__global__ void __launch_bounds__(256, 1) gemm3(GP p)
{
    extern __shared__ __align__(128) char smem[];
    const u32 sb = smem_u32(smem);
    const int tid = threadIdx.x;
    const int lane = tid & 31, wid = tid >> 5;
    const int warp_m = wid & 1, warp_n = wid >> 1;
    const int bm = blockIdx.x * 128;

    const u16* WtH = p.WtH; const u16* WtL = p.WtL; float* Cf = p.Cf;
    if (p.njobs) { int jy = blockIdx.y; WtH = p.jwh[jy]; WtL = p.jwl[jy]; Cf = p.jcf[jy]; }

    const int arow = tid >> 1, ahalf = tid & 1;
    const int gmc = min(bm + arow, p.M - 1);
    const int r0i = p.I0 ? p.I0[gmc] : gmc;
    const int r1i = p.I1 ? p.I1[gmc] : gmc;
    const u16* pa0h = p.A0h ? (p.A0h + (size_t)r0i * p.ld0) : nullptr;
    const u16* pa0l = p.A0l ? (p.A0l + (size_t)r0i * p.ld0) : nullptr;
    const u16* pa1h = p.A1h ? (p.A1h + (size_t)r1i * p.ld1) : nullptr;
    const u16* pa1l = p.A1l ? (p.A1l + (size_t)r1i * p.ld1) : nullptr;
    const u16* pbh = WtH + (size_t)tid * p.Kpad;
    const u16* pbl = WtL + (size_t)tid * p.Kpad;

    float acc[4][8][4];
    #pragma unroll
    for (int a = 0; a < 4; a++)
        #pragma unroll
        for (int b = 0; b < 8; b++)
            #pragma unroll
            for (int c = 0; c < 4; c++) acc[a][b][c] = 0.f;

    auto prefetchB = [&](int c) {
        const int k0 = c << 5;
        u32 db = sb + (c & 1) * STAGE + 20480 + (u32)tid * RSB;
        #pragma unroll
        for (int j = 0; j < 4; j++) {
            cp16(db + j * 16,         pbh + k0 + j * 8);
            cp16(db + 20480 + j * 16, pbl + k0 + j * 8);
        }
    };
    auto prefetchA = [&](int c) {
        const int k0 = c << 5;
        const u32 st = sb + (c & 1) * STAGE;
        const u16 *sh, *sl;
        int kk;
        if (k0 < p.w0) { sh = pa0h; sl = pa0l; kk = k0; }
        else           { sh = pa1h; sl = pa1l; kk = k0 - p.w0; }
        u32 da = st + (u32)arow * RSB + ahalf * 32;
        cp16(da,              sh + kk + ahalf * 16);
        cp16(da + 16,         sh + kk + ahalf * 16 + 8);
        cp16(da + 10240,      sl + kk + ahalf * 16);
        cp16(da + 10240 + 16, sl + kk + ahalf * 16 + 8);
    };

    // ---- COMB state ----
    float eav[6];
    float fu[16], fv[16];
    const float* w1ct = (const float*)(smem + 2 * STAGE);          // [256][8]
    float* eas = (float*)(smem + 2 * STAGE + 8192);                // [128][6]

    auto comb_load = [&](int c) {
        const int kb = (c << 5) + ahalf * 16;
        #pragma unroll
        for (int j = 0; j < 4; j++) {
            *(float4*)&fu[4 * j] = *(const float4*)&p.Uf[(size_t)r0i * 256 + kb + 4 * j];
            *(float4*)&fv[4 * j] = *(const float4*)&p.Vf[(size_t)r1i * 256 + kb + 4 * j];
        }
    };
    auto comb_convert = [&](int c) {
        const int kb = (c << 5) + ahalf * 16;
        const u32 st = sb + (c & 1) * STAGE;
        u32 hw[8], lw[8];
        #pragma unroll
        for (int j = 0; j < 8; j++) {
            float t[2];
            #pragma unroll
            for (int q = 0; q < 2; q++) {
                int k = kb + 2 * j + q;
                float4 wa = *(const float4*)&w1ct[k * 8];
                float4 wb = *(const float4*)&w1ct[k * 8 + 4];
                float v = fu[2 * j + q] + fv[2 * j + q] + wb.z
                        + eav[0] * wa.x + eav[1] * wa.y + eav[2] * wa.z + eav[3] * wa.w
                        + eav[4] * wb.x + eav[5] * wb.y;
                t[q] = fmaxf(v, 0.f);
            }
            u32 b0 = __float_as_uint(t[0]), b1 = __float_as_uint(t[1]);
            hw[j] = (b1 & 0xFFFF0000u) | (b0 >> 16);
            float l0 = t[0] - __uint_as_float(b0 & 0xFFFF0000u);
            float l1 = t[1] - __uint_as_float(b1 & 0xFFFF0000u);
            asm("cvt.rn.bf16x2.f32 %0, %1, %2;" : "=r"(lw[j]) : "f"(l1), "f"(l0));
        }
        u32 da = st + (u32)arow * RSB + ahalf * 32;
        sts128(da,              hw[0], hw[1], hw[2], hw[3]);
        sts128(da + 16,         hw[4], hw[5], hw[6], hw[7]);
        sts128(da + 10240,      lw[0], lw[1], lw[2], lw[3]);
        sts128(da + 10240 + 16, lw[4], lw[5], lw[6], lw[7]);
    };

    // ---- prologue ----
    if constexpr (COMB) {
        float* w1w = (float*)(smem + 2 * STAGE);
        for (int i = tid; i < 2048; i += 256) {
            int k = i >> 3, jj = i & 7;
            float v = 0.f;
            if (jj < 6) v = p.W1c[jj * 256 + k];
            else if (jj == 6) v = p.B1[k];
            w1w[i] = v;
        }
        for (int i = tid; i < 768; i += 256) {
            int e = bm + i / 6, j = i % 6;
            eas[i] = (e < p.M) ? p.EAT[(size_t)e * 6 + j] : 0.f;
        }
        __syncthreads();
        #pragma unroll
        for (int j = 0; j < 6; j++) eav[j] = eas[arow * 6 + j];
        comb_load(0);
        prefetchB(0);
        asm volatile("cp.async.commit_group;" ::: "memory");
        comb_convert(0);
    } else {
        if constexpr (PRED) {
            ((float*)(smem + 2 * STAGE))[tid] = p.PW2[tid];
        }
        prefetchA(0); prefetchB(0);
        asm volatile("cp.async.commit_group;" ::: "memory");
    }

    // ---- mainloop ----
    for (int c = 0; c < p.nch; c++) {
        if (c + 1 < p.nch) {
            if constexpr (COMB) { comb_load(c + 1); prefetchB(c + 1); }
            else { prefetchA(c + 1); prefetchB(c + 1); }
            asm volatile("cp.async.commit_group;" ::: "memory");
            asm volatile("cp.async.wait_group 1;" ::: "memory");
        } else {
            asm volatile("cp.async.wait_group 0;" ::: "memory");
        }
        __syncthreads();

        const u32 st = sb + (c & 1) * STAGE;
        const u32 aH = st, aL = st + 10240, bH = st + 20480, bL = st + 40960;
        #pragma unroll
        for (int kk = 0; kk < 2; kk++) {
            u32 Afh[4][4], Afl[4][4];
            #pragma unroll
            for (int mf = 0; mf < 4; mf++) {
                u32 off = (u32)(warp_m * 64 + mf * 16 + (lane & 15)) * RSB
                        + kk * 32 + ((lane >> 4) << 4);
                ldsm4(Afh[mf], aH + off);
                ldsm4(Afl[mf], aL + off);
            }
            #pragma unroll
            for (int nf = 0; nf < 4; nf++) {
                u32 off = (u32)(warp_n * 64 + nf * 16 + ((lane >> 4) & 1) * 8 + (lane & 7)) * RSB
                        + kk * 32 + ((lane >> 3) & 1) * 16;
                u32 bh[4], bl[4];
                ldsm4(bh, bH + off);
                ldsm4(bl, bL + off);
                #pragma unroll
                for (int mf = 0; mf < 4; mf++) {
                    mma_bf16(acc[mf][2 * nf],     Afh[mf], bh[0], bh[1]);
                    mma_bf16(acc[mf][2 * nf + 1], Afh[mf], bh[2], bh[3]);
                }
                #pragma unroll
                for (int mf = 0; mf < 4; mf++) {
                    mma_bf16(acc[mf][2 * nf],     Afh[mf], bl[0], bl[1]);
                    mma_bf16(acc[mf][2 * nf + 1], Afh[mf], bl[2], bl[3]);
                }
                #pragma unroll
                for (int mf = 0; mf < 4; mf++) {
                    mma_bf16(acc[mf][2 * nf],     Afl[mf], bh[0], bh[1]);
                    mma_bf16(acc[mf][2 * nf + 1], Afl[mf], bh[2], bh[3]);
                }
            }
        }
        if constexpr (COMB) { if (c + 1 < p.nch) comb_convert(c + 1); }
        __syncthreads();
    }

    // ---- epilogue ----
    const int gid = lane >> 2, tig = lane & 3;
    #pragma unroll
    for (int mf = 0; mf < 4; mf++) {
        #pragma unroll
        for (int half = 0; half < 2; half++) {
            const int r = bm + warp_m * 64 + mf * 16 + half * 8 + gid;
            if constexpr (PRED) {
                const float* w2s = (const float*)(smem + 2 * STAGE);
                float s = 0.f;
                if (r < p.M) {
                    #pragma unroll
                    for (int nidx = 0; nidx < 8; nidx++) {
                        const int col = warp_n * 64 + nidx * 8 + tig * 2;
                        float o0 = acc[mf][nidx][half * 2 + 0] + p.bias[col];
                        float o1 = acc[mf][nidx][half * 2 + 1] + p.bias[col + 1];
                        o0 = fmaxf(o0, 0.f); o1 = fmaxf(o1, 0.f);
                        s += o0 * w2s[col] + o1 * w2s[col + 1];
                    }
                }
                s += __shfl_xor_sync(0xffffffffu, s, 1);
                s += __shfl_xor_sync(0xffffffffu, s, 2);
                if (tig == 0 && r < p.M) atomicAdd(&p.OutP[r], s);
            } else if (r < p.M) {
                const float* ag1 = nullptr;
                const float* ag2 = nullptr;
                int sd = 0;
                if (ADD) {
                    ag1 = p.G1 + (size_t)(p.IG1 ? p.IG1[r] : r) * 256;
                    if (p.G2) ag2 = p.G2 + (size_t)(p.IG2 ? p.IG2[r] : r) * 256;
                }
                if (SCAT) sd = p.SDST[r];
                #pragma unroll
                for (int nidx = 0; nidx < 8; nidx++) {
                    const int col = warp_n * 64 + nidx * 8 + tig * 2;
                    float o0 = acc[mf][nidx][half * 2 + 0];
                    float o1 = acc[mf][nidx][half * 2 + 1];
                    if (p.bias) { o0 += p.bias[col]; o1 += p.bias[col + 1]; }
                    if (ADD) {
                        o0 += ag1[col]; o1 += ag1[col + 1];
                        if (ag2) { o0 += ag2[col]; o1 += ag2[col + 1]; }
                    }
                    if (RELU) { o0 = fmaxf(o0, 0.f); o1 = fmaxf(o1, 0.f); }
                    if (RES) {
                        ushort2 rh = *(const ushort2*)&p.ResH[(size_t)r * 256 + col];
                        ushort2 rl = *(const ushort2*)&p.ResL[(size_t)r * 256 + col];
                        o0 += up16(rh.x) + up16(rl.x);
                        o1 += up16(rh.y) + up16(rl.y);
                    }
                    if (SCAT) {
                        atomicAdd(&Cf[(size_t)sd * 256 + col],     o0);
                        atomicAdd(&Cf[(size_t)sd * 256 + col + 1], o1);
                    } else if (SPLIT) {
                        u32 hp, lp;
                        split2(o0, o1, hp, lp);
                        *(u32*)&p.Ch[(size_t)r * 256 + col] = hp;
                        *(u32*)&p.Cl[(size_t)r * 256 + col] = lp;
                    } else {
                        *(float2*)&Cf[(size_t)r * 256 + col] = make_float2(o0, o1);
                    }
                }
            }
        }
    }
}

extern "C" void kernel_launch(void* const* d_in, const int* in_sizes, int n_in,
                              void* d_out, int out_size)
{
    const float* x      = (const float*)d_in[0];
    const int*   ei32   = (const int*)d_in[1];
    const float* eattr  = (const float*)d_in[2];
    const float* e_w1_0 = (const float*)d_in[3];
    const float* e_b1_0 = (const float*)d_in[4];
    const float* e_w2_0 = (const float*)d_in[5];
    const float* e_b2_0 = (const float*)d_in[6];
    const float* n_wm_0 = (const float*)d_in[7];
    const float* n_bm_0 = (const float*)d_in[8];
    const float* n_w1_0 = (const float*)d_in[9];
    const float* n_b1_0 = (const float*)d_in[10];
    const float* n_w2_0 = (const float*)d_in[11];
    const float* n_b2_0 = (const float*)d_in[12];
    const float* e_w1_1 = (const float*)d_in[13];
    const float* e_b1_1 = (const float*)d_in[14];
    const float* e_w2_1 = (const float*)d_in[15];
    const float* e_b2_1 = (const float*)d_in[16];
    // d_in[17..22]: layer-1 node model — dead code for the output
    const float* p_w1   = (const float*)d_in[23];
    const float* p_b1   = (const float*)d_in[24];
    const float* p_w2   = (const float*)d_in[25];
    const float* p_b2   = (const float*)d_in[26];
    float* out = (float*)d_out;

#define SYM(T, v, s) T* v; cudaGetSymbolAddress((void**)&v, s)
    SYM(u16, XFh, g_XFh); SYM(u16, XFl, g_XFl);
    SYM(u16, EAh, g_EAh); SYM(u16, EAl, g_EAl);
    SYM(u16, EHh, g_EHh); SYM(u16, EHl, g_EHl);
    SYM(u16, E2h, g_E2h); SYM(u16, E2l, g_E2l);
    SYM(u16, Shh, g_Shh); SYM(u16, Sll, g_Sll);
    SYM(u16, XHh, g_XHh); SYM(u16, XHl, g_XHl);
    SYM(u16, X1h, g_X1h); SYM(u16, X1l, g_X1l);
    SYM(float, U, g_U); SYM(float, V, g_V); SYM(float, P, g_P);
    SYM(float, S, g_S);
    SYM(int, SRC, g_SRC); SYM(int, DST, g_DST);
    SYM(u16, WTH, g_WTH); SYM(u16, WTL, g_WTL);
#undef SYM

#define P0 gemm3<false, false, false, false, false, false, false>
#define PC gemm3<false, false, true,  false, false, true,  false>
#define P3 gemm3<true,  false, false, true,  true,  false, false>
#define P1 gemm3<true,  false, true,  false, false, false, false>
#define P2 gemm3<false, false, true,  false, false, false, false>
#define P4 gemm3<true,  false, true,  true,  false, false, false>
#define P5 gemm3<false, true,  true,  false, false, false, false>
#define P6 gemm3<true,  false, false, false, false, false, true >
    cudaFuncSetAttribute(P0, cudaFuncAttributeMaxDynamicSharedMemorySize, SMEM_SZ);
    cudaFuncSetAttribute(PC, cudaFuncAttributeMaxDynamicSharedMemorySize, SMEM_SZ);
    cudaFuncSetAttribute(P3, cudaFuncAttributeMaxDynamicSharedMemorySize, SMEM_SZ);
    cudaFuncSetAttribute(P1, cudaFuncAttributeMaxDynamicSharedMemorySize, SMEM_SZ);
    cudaFuncSetAttribute(P2, cudaFuncAttributeMaxDynamicSharedMemorySize, SMEM_SZ);
    cudaFuncSetAttribute(P4, cudaFuncAttributeMaxDynamicSharedMemorySize, SMEM_SZ);
    cudaFuncSetAttribute(P5, cudaFuncAttributeMaxDynamicSharedMemorySize, SMEM_SZ);
    cudaFuncSetAttribute(P6, cudaFuncAttributeMaxDynamicSharedMemorySize, SMEM_SZ);

    // one batched weight split (offsets in k-units)
    WtJobs wj = {{
        { e_w1_0,             512, 0    },   // W1a
        { e_w1_0 + 512 * 256, 512, 512  },   // W1b
        { e_w2_0,             256, 1024 },
        { n_wm_0,             512, 1280 },   // Wm_a
        { n_wm_0 + 512 * 256, 256, 1792 },   // Wm_b
        { n_w1_0,             768, 2048 },
        { n_w2_0,             256, 2816 },
        { e_w1_1,             256, 3072 },   // W11a
        { e_w1_1 + 256 * 256, 256, 3328 },   // W11b
        { e_w1_1 + 512 * 256, 256, 3584 },   // W11c
        { e_w2_1,             256, 3840 },
        { p_w1,               256, 4096 },
    }};
    wt_all<<<dim3(768, 12), 256>>>(wj);

    detect_kernel<<<1, 256>>>(ei32);
    prep_kernel<<<2048, 256>>>(ei32, out, p_b2);
    count_kernel<<<(NE + 255) / 256, 256>>>();
    split_kernel<<<(NN * 512 + 255) / 256, 256>>>(x, NN * 512, XFh, XFl);

    GP a{};
    dim3 blk(256);

    // ---- batch: U = x@W1a, V = x@W1b, P = x@Wm_a ----
    a = GP{};
    a.M = NN; a.nch = 16; a.Kpad = 512;
    a.A0h = XFh; a.A0l = XFl; a.w0 = 512; a.ld0 = 512;
    a.jwh[0] = WTH;              a.jwl[0] = WTL;              a.jcf[0] = U;
    a.jwh[1] = WTH + 256 * 512;  a.jwl[1] = WTL + 256 * 512;  a.jcf[1] = V;
    a.jwh[2] = WTH + 256 * 1280; a.jwl[2] = WTL + 256 * 1280; a.jcf[2] = P;
    a.njobs = 3;
    P0<<<dim3(79, 3), blk, SMEM_SZ>>>(a);

    // ---- EA = (relu(U[src]+V[dst]+ea@W1c+b1)) @ e_w2_0 + b2  [COMB fused] ----
    a = GP{};
    a.M = NE; a.nch = 8; a.Kpad = 256;
    a.I0 = SRC; a.I1 = DST; a.w0 = 256;
    a.Uf = U; a.Vf = V; a.EAT = eattr;
    a.W1c = e_w1_0 + (size_t)1024 * 256; a.B1 = e_b1_0;
    a.WtH = WTH + 256 * 1024; a.WtL = WTL + 256 * 1024;
    a.bias = e_b2_0; a.Ch = EAh; a.Cl = EAl;
    PC<<<dim3(1250), blk, SMEM_SZ>>>(a);

    // ---- MSG = relu(EA@Wm_b + P[src] + bm) scattered into S[dst] ----
    a = GP{};
    a.M = NE; a.nch = 8; a.Kpad = 256;
    a.A0h = EAh; a.A0l = EAl; a.w0 = 256; a.ld0 = 256;
    a.WtH = WTH + 256 * 1792; a.WtL = WTL + 256 * 1792;
    a.bias = n_bm_0; a.G1 = P; a.IG1 = SRC; a.SDST = DST; a.Cf = S;
    P3<<<dim3(1250), blk, SMEM_SZ>>>(a);
    mean_kernel<<<NN, 256>>>();

    // ---- XH = relu([x, S] @ n_w1_0 + b) ----
    a = GP{};
    a.M = NN; a.nch = 24; a.Kpad = 768;
    a.A0h = XFh; a.A0l = XFl; a.w0 = 512; a.ld0 = 512;
    a.A1h = Shh; a.A1l = Sll; a.ld1 = 256;
    a.WtH = WTH + 256 * 2048; a.WtL = WTL + 256 * 2048;
    a.bias = n_b1_0; a.Ch = XHh; a.Cl = XHl;
    P1<<<dim3(79), blk, SMEM_SZ>>>(a);

    // ---- X1 = XH @ n_w2_0 + b ----
    a = GP{};
    a.M = NN; a.nch = 8; a.Kpad = 256;
    a.A0h = XHh; a.A0l = XHl; a.w0 = 256; a.ld0 = 256;
    a.WtH = WTH + 256 * 2816; a.WtL = WTL + 256 * 2816;
    a.bias = n_b2_0; a.Ch = X1h; a.Cl = X1l;
    P2<<<dim3(79), blk, SMEM_SZ>>>(a);

    // ---- batch: U1 = X1@W11a, V1 = X1@W11b ----
    a = GP{};
    a.M = NN; a.nch = 8; a.Kpad = 256;
    a.A0h = X1h; a.A0l = X1l; a.w0 = 256; a.ld0 = 256;
    a.jwh[0] = WTH + 256 * 3072; a.jwl[0] = WTL + 256 * 3072; a.jcf[0] = U;
    a.jwh[1] = WTH + 256 * 3328; a.jwl[1] = WTL + 256 * 3328; a.jcf[1] = V;
    a.njobs = 2;
    P0<<<dim3(79, 2), blk, SMEM_SZ>>>(a);

    // ---- EH2 = relu(EA@W11c + U1[src] + V1[dst] + b) ----
    a = GP{};
    a.M = NE; a.nch = 8; a.Kpad = 256;
    a.A0h = EAh; a.A0l = EAl; a.w0 = 256; a.ld0 = 256;
    a.WtH = WTH + 256 * 3584; a.WtL = WTL + 256 * 3584;
    a.bias = e_b1_1; a.G1 = U; a.IG1 = SRC; a.G2 = V; a.IG2 = DST;
    a.Ch = EHh; a.Cl = EHl;
    P4<<<dim3(1250), blk, SMEM_SZ>>>(a);

    // ---- EA2 = EH2 @ e_w2_1 + b + EA ----
    a = GP{};
    a.M = NE; a.nch = 8; a.Kpad = 256;
    a.A0h = EHh; a.A0l = EHl; a.w0 = 256; a.ld0 = 256;
    a.WtH = WTH + 256 * 3840; a.WtL = WTL + 256 * 3840;
    a.bias = e_b2_1; a.ResH = EAh; a.ResL = EAl; a.Ch = E2h; a.Cl = E2l;
    P5<<<dim3(1250), blk, SMEM_SZ>>>(a);

    // ---- out = relu(EA2@p_w1 + b1) @ p_w2 + b2  [PRED fused] ----
    a = GP{};
    a.M = NE; a.nch = 8; a.Kpad = 256;
    a.A0h = E2h; a.A0l = E2l; a.w0 = 256; a.ld0 = 256;
    a.WtH = WTH + 256 * 4096; a.WtL = WTL + 256 * 4096;
    a.bias = p_b1; a.PW2 = p_w2; a.OutP = out;
    P6<<<dim3(1250), blk, SMEM_SZ>>>(a);

    (void)in_sizes; (void)n_in; (void)out_size;
}

// round 8
// speedup vs baseline: 4.7527x; 1.0807x over previous
#include <cuda_runtime.h>
#include <cuda_bf16.h>
#include <cstdint>
#include <cstddef>

#define NE 160000
#define NN 10000
typedef unsigned short u16;
typedef unsigned int u32;

// ---------------- scratch (device globals) ----------------
__device__ u16 g_XFh[(size_t)NN * 512], g_XFl[(size_t)NN * 512];
__device__ u16 g_EAh[(size_t)NE * 256], g_EAl[(size_t)NE * 256];
__device__ u16 g_EHh[(size_t)NE * 256], g_EHl[(size_t)NE * 256];
__device__ u16 g_Shh[NN * 256], g_Sll[NN * 256];
__device__ u16 g_XHh[NN * 256], g_XHl[NN * 256];
__device__ float g_U[NN * 256], g_V[NN * 256], g_P[NN * 256];
__device__ float g_S[NN * 256];
__device__ float g_CNT[NN];
__device__ float g_BC[768];            // bc_a | bc_b | bc_p
__device__ int   g_SRC[NE], g_DST[NE];
__device__ int   g_IS64;
__device__ u16 g_WTH[256 * 4416], g_WTL[256 * 4416];

// ---------------- helpers ----------------
__device__ __forceinline__ u32 smem_u32(const void* p) {
    u32 a;
    asm("{ .reg .u64 t; cvta.to.shared.u64 t, %1; cvt.u32.u64 %0, t; }" : "=r"(a) : "l"(p));
    return a;
}
__device__ __forceinline__ void cp16(u32 dst, const void* src) {
    asm volatile("cp.async.ca.shared.global [%0], [%1], 16;" :: "r"(dst), "l"(src) : "memory");
}
__device__ __forceinline__ void ldsm4(u32* r, u32 addr) {
    asm volatile("ldmatrix.sync.aligned.m8n8.x4.shared.b16 {%0,%1,%2,%3}, [%4];"
                 : "=r"(r[0]), "=r"(r[1]), "=r"(r[2]), "=r"(r[3]) : "r"(addr));
}
__device__ __forceinline__ void mma_bf16(float* d, const u32* a, u32 b0, u32 b1) {
    asm volatile(
        "mma.sync.aligned.m16n8k16.row.col.f32.bf16.bf16.f32 "
        "{%0,%1,%2,%3}, {%4,%5,%6,%7}, {%8,%9}, {%0,%1,%2,%3};"
        : "+f"(d[0]), "+f"(d[1]), "+f"(d[2]), "+f"(d[3])
        : "r"(a[0]), "r"(a[1]), "r"(a[2]), "r"(a[3]), "r"(b0), "r"(b1));
}
__device__ __forceinline__ float up16(u16 u) { return __uint_as_float(((u32)u) << 16); }
__device__ __forceinline__ void sts128(u32 addr, u32 a, u32 b, u32 c, u32 d) {
    asm volatile("st.shared.v4.b32 [%0], {%1,%2,%3,%4};" :: "r"(addr), "r"(a), "r"(b), "r"(c), "r"(d) : "memory");
}
__device__ __forceinline__ void split2(float o0, float o1, u32& hp, u32& lp) {
    u32 b0 = __float_as_uint(o0), b1 = __float_as_uint(o1);
    hp = (b1 & 0xFFFF0000u) | (b0 >> 16);
    float l0 = o0 - __uint_as_float(b0 & 0xFFFF0000u);
    float l1 = o1 - __uint_as_float(b1 & 0xFFFF0000u);
    asm("cvt.rn.bf16x2.f32 %0, %1, %2;" : "=r"(lp) : "f"(l1), "f"(l0));
}
__device__ __forceinline__ void wt_store(size_t o, float v) {
    u32 b = __float_as_uint(v);
    g_WTH[o] = (u16)(b >> 16);
    __nv_bfloat16 lo = __float2bfloat16_rn(v - __uint_as_float(b & 0xFFFF0000u));
    g_WTL[o] = *(u16*)&lo;
}

#define RSB   80
#define STAGE 61440
#define EXTRA 11264
#define SMEM_SZ (2 * STAGE + EXTRA)

// ---------------- batched weight split/transpose ----------------
struct WtEnt { const float* w; int K, off, stride, kofs; };
struct WtJobs { WtEnt e[8]; };

__global__ void wt_all(WtJobs ja) {
    const WtEnt en = ja.e[blockIdx.y];
    int idx = blockIdx.x * blockDim.x + threadIdx.x;
    if (idx >= 256 * en.K) return;
    int n = idx / en.K, k = idx - n * en.K;
    wt_store((size_t)256 * en.off + (size_t)n * en.stride + en.kofs + k,
             en.w[(size_t)k * 256 + n]);
}

// compose_w: Wc[k,n] = sum_m A[k,m] * B[m,n], split-stored transposed
struct CompJob { const float* A; const float* B; int off, stride; };
struct CompJobs { CompJob e[3]; };

__global__ void compose_w(CompJobs ja) {
    const CompJob en = ja.e[blockIdx.y];
    __shared__ float arow[256];
    int k = blockIdx.x, n = threadIdx.x;
    arow[n] = en.A[(size_t)k * 256 + n];
    __syncthreads();
    float s = 0.f;
    #pragma unroll 8
    for (int m = 0; m < 256; m++) s += arow[m] * en.B[(size_t)m * 256 + n];
    wt_store((size_t)256 * en.off + (size_t)n * en.stride + k, s);
}

// compose_b: bc_a = n_b2_0@W11a ; bc_b = n_b2_0@W11b ; bc_p = e_b2_1@p_w1 + p_b1
__global__ void compose_b(const float* __restrict__ n_b2_0, const float* __restrict__ W11a,
                          const float* __restrict__ W11b, const float* __restrict__ e_b2_1,
                          const float* __restrict__ p_w1, const float* __restrict__ p_b1) {
    int n = threadIdx.x;
    float sa = 0.f, sb = 0.f, sp = 0.f;
    for (int m = 0; m < 256; m++) {
        float b2 = n_b2_0[m], e2 = e_b2_1[m];
        sa += b2 * W11a[(size_t)m * 256 + n];
        sb += b2 * W11b[(size_t)m * 256 + n];
        sp += e2 * p_w1[(size_t)m * 256 + n];
    }
    g_BC[n] = sa;
    g_BC[256 + n] = sb;
    g_BC[512 + n] = sp + p_b1[n];
}

__global__ void split_kernel(const float* __restrict__ src, int n,
                             u16* __restrict__ H, u16* __restrict__ L) {
    int i = blockIdx.x * blockDim.x + threadIdx.x;
    if (i >= n) return;
    float v = src[i];
    u32 b = __float_as_uint(v);
    H[i] = (u16)(b >> 16);
    __nv_bfloat16 lo = __float2bfloat16_rn(v - __uint_as_float(b & 0xFFFF0000u));
    L[i] = *(u16*)&lo;
}

__global__ void detect_kernel(const int* __restrict__ ei32) {
    __shared__ int any_nonzero;
    if (threadIdx.x == 0) any_nonzero = 0;
    __syncthreads();
    for (int i = threadIdx.x; i < 2048; i += blockDim.x) {
        int pos = 2 * (i * (NE / 2048)) + 1;
        if (ei32[pos] != 0) any_nonzero = 1;
    }
    __syncthreads();
    if (threadIdx.x == 0) g_IS64 = any_nonzero ? 0 : 1;
}

__global__ void prep_kernel(const int* __restrict__ ei32, float* __restrict__ outp,
                            const float* __restrict__ b2) {
    int i = blockIdx.x * blockDim.x + threadIdx.x;
    int stride = gridDim.x * blockDim.x;
    const int is64 = g_IS64;
    const float bv = b2[0];
    for (int j = i; j < NN * 256; j += stride) g_S[j] = 0.f;
    for (int j = i; j < NN; j += stride) g_CNT[j] = 0.f;
    for (int j = i; j < NE; j += stride) {
        int s, d;
        if (is64) { s = ei32[2 * j]; d = ei32[2 * (NE + j)]; }
        else      { s = ei32[j];     d = ei32[NE + j]; }
        g_SRC[j] = min(max(s, 0), NN - 1);
        g_DST[j] = min(max(d, 0), NN - 1);
        outp[j] = bv;
    }
}

__global__ void count_kernel() {
    int e = blockIdx.x * blockDim.x + threadIdx.x;
    if (e < NE) atomicAdd(&g_CNT[g_DST[e]], 1.f);
}

__global__ void mean_kernel() {
    int n = blockIdx.x, c = threadIdx.x;
    float v = g_S[n * 256 + c] / fmaxf(g_CNT[n], 1.f);
    u32 b = __float_as_uint(v);
    g_Shh[n * 256 + c] = (u16)(b >> 16);
    __nv_bfloat16 lo = __float2bfloat16_rn(v - __uint_as_float(b & 0xFFFF0000u));
    g_Sll[n * 256 + c] = *(u16*)&lo;
}

// ---------------- unified HMMA GEMM ----------------
struct GP {
    int M, nch, Kpad;
    const u16 *A0h, *A0l; const int* I0; int w0, ld0;
    const u16 *A1h, *A1l; const int* I1; int ld1;
    const u16 *WtH, *WtL;
    const float* bias;
    const float* G1; const int* IG1;
    const float* G2; const int* IG2;
    const int* SDST;
    float* Cf; u16 *Ch, *Cl;
    const float *Uf, *Vf, *EAT, *W1c, *B1;   // COMB
    const float* PW2; float* OutP;           // PRED
    const u16* jwh[3]; const u16* jwl[3]; float* jcf[3]; const float* jb[3]; int njobs;
};

template<bool RELU, bool SPLIT, bool ADD, bool SCAT, bool COMB, bool PRED>
__global__ void __launch_bounds__(256, 1) gemm3(GP p)
{
    extern __shared__ __align__(128) char smem[];
    const u32 sb = smem_u32(smem);
    const int tid = threadIdx.x;
    const int lane = tid & 31, wid = tid >> 5;
    const int warp_m = wid & 1, warp_n = wid >> 1;
    const int bm = blockIdx.x * 128;

    const u16* WtH = p.WtH; const u16* WtL = p.WtL; float* Cf = p.Cf;
    const float* bias = p.bias;
    if (p.njobs) {
        int jy = blockIdx.y;
        WtH = p.jwh[jy]; WtL = p.jwl[jy]; Cf = p.jcf[jy]; bias = p.jb[jy];
    }

    const int arow = tid >> 1, ahalf = tid & 1;
    const int gmc = min(bm + arow, p.M - 1);
    const int r0i = p.I0 ? p.I0[gmc] : gmc;
    const int r1i = p.I1 ? p.I1[gmc] : gmc;
    const u16* pa0h = p.A0h ? (p.A0h + (size_t)r0i * p.ld0) : nullptr;
    const u16* pa0l = p.A0l ? (p.A0l + (size_t)r0i * p.ld0) : nullptr;
    const u16* pa1h = p.A1h ? (p.A1h + (size_t)r1i * p.ld1) : nullptr;
    const u16* pa1l = p.A1l ? (p.A1l + (size_t)r1i * p.ld1) : nullptr;
    const u16* pbh = WtH + (size_t)tid * p.Kpad;
    const u16* pbl = WtL + (size_t)tid * p.Kpad;

    float acc[4][8][4];
    #pragma unroll
    for (int a = 0; a < 4; a++)
        #pragma unroll
        for (int b = 0; b < 8; b++)
            #pragma unroll
            for (int c = 0; c < 4; c++) acc[a][b][c] = 0.f;

    auto prefetchB = [&](int c) {
        const int k0 = c << 5;
        u32 db = sb + (c & 1) * STAGE + 20480 + (u32)tid * RSB;
        #pragma unroll
        for (int j = 0; j < 4; j++) {
            cp16(db + j * 16,         pbh + k0 + j * 8);
            cp16(db + 20480 + j * 16, pbl + k0 + j * 8);
        }
    };
    auto prefetchA = [&](int c) {
        const int k0 = c << 5;
        const u32 st = sb + (c & 1) * STAGE;
        const u16 *sh, *sl;
        int kk;
        if (k0 < p.w0) { sh = pa0h; sl = pa0l; kk = k0; }
        else           { sh = pa1h; sl = pa1l; kk = k0 - p.w0; }
        u32 da = st + (u32)arow * RSB + ahalf * 32;
        cp16(da,              sh + kk + ahalf * 16);
        cp16(da + 16,         sh + kk + ahalf * 16 + 8);
        cp16(da + 10240,      sl + kk + ahalf * 16);
        cp16(da + 10240 + 16, sl + kk + ahalf * 16 + 8);
    };

    // ---- COMB state ----
    float eav[6];
    float fu[16], fv[16];
    const float* w1ct = (const float*)(smem + 2 * STAGE);
    float* eas = (float*)(smem + 2 * STAGE + 8192);

    auto comb_load = [&](int c) {
        const int kb = (c << 5) + ahalf * 16;
        #pragma unroll
        for (int j = 0; j < 4; j++) {
            *(float4*)&fu[4 * j] = *(const float4*)&p.Uf[(size_t)r0i * 256 + kb + 4 * j];
            *(float4*)&fv[4 * j] = *(const float4*)&p.Vf[(size_t)r1i * 256 + kb + 4 * j];
        }
    };
    auto comb_convert = [&](int c) {
        const int kb = (c << 5) + ahalf * 16;
        const u32 st = sb + (c & 1) * STAGE;
        u32 hw[8], lw[8];
        #pragma unroll
        for (int j = 0; j < 8; j++) {
            float t[2];
            #pragma unroll
            for (int q = 0; q < 2; q++) {
                int k = kb + 2 * j + q;
                float4 wa = *(const float4*)&w1ct[k * 8];
                float4 wb = *(const float4*)&w1ct[k * 8 + 4];
                float v = fu[2 * j + q] + fv[2 * j + q] + wb.z
                        + eav[0] * wa.x + eav[1] * wa.y + eav[2] * wa.z + eav[3] * wa.w
                        + eav[4] * wb.x + eav[5] * wb.y;
                t[q] = fmaxf(v, 0.f);
            }
            u32 b0 = __float_as_uint(t[0]), b1 = __float_as_uint(t[1]);
            hw[j] = (b1 & 0xFFFF0000u) | (b0 >> 16);
            float l0 = t[0] - __uint_as_float(b0 & 0xFFFF0000u);
            float l1 = t[1] - __uint_as_float(b1 & 0xFFFF0000u);
            asm("cvt.rn.bf16x2.f32 %0, %1, %2;" : "=r"(lw[j]) : "f"(l1), "f"(l0));
        }
        u32 da = st + (u32)arow * RSB + ahalf * 32;
        sts128(da,              hw[0], hw[1], hw[2], hw[3]);
        sts128(da + 16,         hw[4], hw[5], hw[6], hw[7]);
        sts128(da + 10240,      lw[0], lw[1], lw[2], lw[3]);
        sts128(da + 10240 + 16, lw[4], lw[5], lw[6], lw[7]);
    };

    // ---- prologue ----
    if constexpr (COMB) {
        float* w1w = (float*)(smem + 2 * STAGE);
        for (int i = tid; i < 2048; i += 256) {
            int k = i >> 3, jj = i & 7;
            float v = 0.f;
            if (jj < 6) v = p.W1c[jj * 256 + k];
            else if (jj == 6) v = p.B1[k];
            w1w[i] = v;
        }
        for (int i = tid; i < 768; i += 256) {
            int e = bm + i / 6, j = i % 6;
            eas[i] = (e < p.M) ? p.EAT[(size_t)e * 6 + j] : 0.f;
        }
        __syncthreads();
        #pragma unroll
        for (int j = 0; j < 6; j++) eav[j] = eas[arow * 6 + j];
        comb_load(0);
        prefetchB(0);
        asm volatile("cp.async.commit_group;" ::: "memory");
        comb_convert(0);
    } else {
        if constexpr (PRED) {
            ((float*)(smem + 2 * STAGE))[tid] = p.PW2[tid];
        }
        prefetchA(0); prefetchB(0);
        asm volatile("cp.async.commit_group;" ::: "memory");
    }

    // ---- mainloop ----
    for (int c = 0; c < p.nch; c++) {
        if (c + 1 < p.nch) {
            if constexpr (COMB) { comb_load(c + 1); prefetchB(c + 1); }
            else { prefetchA(c + 1); prefetchB(c + 1); }
            asm volatile("cp.async.commit_group;" ::: "memory");
            asm volatile("cp.async.wait_group 1;" ::: "memory");
        } else {
            asm volatile("cp.async.wait_group 0;" ::: "memory");
        }
        __syncthreads();

        const u32 st = sb + (c & 1) * STAGE;
        const u32 aH = st, aL = st + 10240, bH = st + 20480, bL = st + 40960;
        #pragma unroll
        for (int kk = 0; kk < 2; kk++) {
            u32 Afh[4][4], Afl[4][4];
            #pragma unroll
            for (int mf = 0; mf < 4; mf++) {
                u32 off = (u32)(warp_m * 64 + mf * 16 + (lane & 15)) * RSB
                        + kk * 32 + ((lane >> 4) << 4);
                ldsm4(Afh[mf], aH + off);
                ldsm4(Afl[mf], aL + off);
            }
            #pragma unroll
            for (int nf = 0; nf < 4; nf++) {
                u32 off = (u32)(warp_n * 64 + nf * 16 + ((lane >> 4) & 1) * 8 + (lane & 7)) * RSB
                        + kk * 32 + ((lane >> 3) & 1) * 16;
                u32 bh[4], bl[4];
                ldsm4(bh, bH + off);
                ldsm4(bl, bL + off);
                #pragma unroll
                for (int mf = 0; mf < 4; mf++) {
                    mma_bf16(acc[mf][2 * nf],     Afh[mf], bh[0], bh[1]);
                    mma_bf16(acc[mf][2 * nf + 1], Afh[mf], bh[2], bh[3]);
                }
                #pragma unroll
                for (int mf = 0; mf < 4; mf++) {
                    mma_bf16(acc[mf][2 * nf],     Afh[mf], bl[0], bl[1]);
                    mma_bf16(acc[mf][2 * nf + 1], Afh[mf], bl[2], bl[3]);
                }
                #pragma unroll
                for (int mf = 0; mf < 4; mf++) {
                    mma_bf16(acc[mf][2 * nf],     Afl[mf], bh[0], bh[1]);
                    mma_bf16(acc[mf][2 * nf + 1], Afl[mf], bh[2], bh[3]);
                }
            }
        }
        if constexpr (COMB) { if (c + 1 < p.nch) comb_convert(c + 1); }
        __syncthreads();
    }

    // ---- epilogue ----
    const int gid = lane >> 2, tig = lane & 3;
    #pragma unroll
    for (int mf = 0; mf < 4; mf++) {
        #pragma unroll
        for (int half = 0; half < 2; half++) {
            const int r = bm + warp_m * 64 + mf * 16 + half * 8 + gid;
            if constexpr (PRED) {
                const float* w2s = (const float*)(smem + 2 * STAGE);
                float s = 0.f;
                if (r < p.M) {
                    #pragma unroll
                    for (int nidx = 0; nidx < 8; nidx++) {
                        const int col = warp_n * 64 + nidx * 8 + tig * 2;
                        float o0 = acc[mf][nidx][half * 2 + 0] + p.bias[col];
                        float o1 = acc[mf][nidx][half * 2 + 1] + p.bias[col + 1];
                        o0 = fmaxf(o0, 0.f); o1 = fmaxf(o1, 0.f);
                        s += o0 * w2s[col] + o1 * w2s[col + 1];
                    }
                }
                s += __shfl_xor_sync(0xffffffffu, s, 1);
                s += __shfl_xor_sync(0xffffffffu, s, 2);
                if (tig == 0 && r < p.M) atomicAdd(&p.OutP[r], s);
            } else if (r < p.M) {
                const float* ag1 = nullptr;
                const float* ag2 = nullptr;
                int sd = 0;
                if (ADD) {
                    ag1 = p.G1 + (size_t)(p.IG1 ? p.IG1[r] : r) * 256;
                    if (p.G2) ag2 = p.G2 + (size_t)(p.IG2 ? p.IG2[r] : r) * 256;
                }
                if (SCAT) sd = p.SDST[r];
                #pragma unroll
                for (int nidx = 0; nidx < 8; nidx++) {
                    const int col = warp_n * 64 + nidx * 8 + tig * 2;
                    float o0 = acc[mf][nidx][half * 2 + 0];
                    float o1 = acc[mf][nidx][half * 2 + 1];
                    if (bias) { o0 += bias[col]; o1 += bias[col + 1]; }
                    if (ADD) {
                        o0 += ag1[col]; o1 += ag1[col + 1];
                        if (ag2) { o0 += ag2[col]; o1 += ag2[col + 1]; }
                    }
                    if (RELU) { o0 = fmaxf(o0, 0.f); o1 = fmaxf(o1, 0.f); }
                    if (SCAT) {
                        asm volatile("red.global.add.v2.f32 [%0], {%1,%2};"
                                     :: "l"(&Cf[(size_t)sd * 256 + col]), "f"(o0), "f"(o1)
                                     : "memory");
                    } else if (SPLIT) {
                        u32 hp, lp;
                        split2(o0, o1, hp, lp);
                        *(u32*)&p.Ch[(size_t)r * 256 + col] = hp;
                        *(u32*)&p.Cl[(size_t)r * 256 + col] = lp;
                    } else {
                        *(float2*)&Cf[(size_t)r * 256 + col] = make_float2(o0, o1);
                    }
                }
            }
        }
    }
}

extern "C" void kernel_launch(void* const* d_in, const int* in_sizes, int n_in,
                              void* d_out, int out_size)
{
    const float* x      = (const float*)d_in[0];
    const int*   ei32   = (const int*)d_in[1];
    const float* eattr  = (const float*)d_in[2];
    const float* e_w1_0 = (const float*)d_in[3];
    const float* e_b1_0 = (const float*)d_in[4];
    const float* e_w2_0 = (const float*)d_in[5];
    const float* e_b2_0 = (const float*)d_in[6];
    const float* n_wm_0 = (const float*)d_in[7];
    const float* n_bm_0 = (const float*)d_in[8];
    const float* n_w1_0 = (const float*)d_in[9];
    const float* n_b1_0 = (const float*)d_in[10];
    const float* n_w2_0 = (const float*)d_in[11];
    const float* n_b2_0 = (const float*)d_in[12];
    const float* e_w1_1 = (const float*)d_in[13];
    const float* e_b1_1 = (const float*)d_in[14];
    const float* e_w2_1 = (const float*)d_in[15];
    const float* e_b2_1 = (const float*)d_in[16];
    // d_in[17..22]: layer-1 node model — dead code for the output
    const float* p_w1   = (const float*)d_in[23];
    const float* p_b1   = (const float*)d_in[24];
    const float* p_w2   = (const float*)d_in[25];
    const float* p_b2   = (const float*)d_in[26];
    float* out = (float*)d_out;

#define SYM(T, v, s) T* v; cudaGetSymbolAddress((void**)&v, s)
    SYM(u16, XFh, g_XFh); SYM(u16, XFl, g_XFl);
    SYM(u16, EAh, g_EAh); SYM(u16, EAl, g_EAl);
    SYM(u16, EHh, g_EHh); SYM(u16, EHl, g_EHl);
    SYM(u16, Shh, g_Shh); SYM(u16, Sll, g_Sll);
    SYM(u16, XHh, g_XHh); SYM(u16, XHl, g_XHl);
    SYM(float, U, g_U); SYM(float, V, g_V); SYM(float, P, g_P);
    SYM(float, S, g_S); SYM(float, BC, g_BC);
    SYM(int, SRC, g_SRC); SYM(int, DST, g_DST);
    SYM(u16, WTH, g_WTH); SYM(u16, WTL, g_WTL);
#undef SYM

#define P0 gemm3<false, false, false, false, false, false>
#define PC gemm3<false, true,  false, false, true,  false>
#define P3 gemm3<true,  false, true,  true,  false, false>
#define P1 gemm3<true,  true,  false, false, false, false>
#define P4 gemm3<true,  true,  true,  false, false, false>
#define P6 gemm3<true,  false, false, false, false, true >
    cudaFuncSetAttribute(P0, cudaFuncAttributeMaxDynamicSharedMemorySize, SMEM_SZ);
    cudaFuncSetAttribute(PC, cudaFuncAttributeMaxDynamicSharedMemorySize, SMEM_SZ);
    cudaFuncSetAttribute(P3, cudaFuncAttributeMaxDynamicSharedMemorySize, SMEM_SZ);
    cudaFuncSetAttribute(P1, cudaFuncAttributeMaxDynamicSharedMemorySize, SMEM_SZ);
    cudaFuncSetAttribute(P4, cudaFuncAttributeMaxDynamicSharedMemorySize, SMEM_SZ);
    cudaFuncSetAttribute(P6, cudaFuncAttributeMaxDynamicSharedMemorySize, SMEM_SZ);

    // weight map (k-units): W1a@0(512) W1b@512(512) e_w2_0@1024(256) Wm_a@1280(512)
    // Wm_b@1792(256) n_w1_0@2048(768) W11c@2816(256) [pred W21@p_w1 | p_w1]@3072(K=512)
    // Wc_a@3584(256) Wc_b@3840(256)
    WtJobs wj = {{
        { e_w1_0,             512, 0,    512, 0 },
        { e_w1_0 + 512 * 256, 512, 512,  512, 0 },
        { e_w2_0,             256, 1024, 256, 0 },
        { n_wm_0,             512, 1280, 512, 0 },
        { n_wm_0 + 512 * 256, 256, 1792, 256, 0 },
        { n_w1_0,             768, 2048, 768, 0 },
        { e_w1_1 + 512 * 256, 256, 2816, 256, 0 },
        { p_w1,               256, 3072, 512, 256 },   // pred K-seg 1
    }};
    wt_all<<<dim3(768, 8), 256>>>(wj);

    CompJobs cj = {{
        { n_w2_0, e_w1_1,             3584, 256 },   // Wc_a
        { n_w2_0, e_w1_1 + 256 * 256, 3840, 256 },   // Wc_b
        { e_w2_1, p_w1,               3072, 512 },   // pred K-seg 0 (W21 @ p_w1)
    }};
    compose_w<<<dim3(256, 3), 256>>>(cj);
    compose_b<<<1, 256>>>(n_b2_0, e_w1_1, e_w1_1 + 256 * 256, e_b2_1, p_w1, p_b1);

    detect_kernel<<<1, 256>>>(ei32);
    prep_kernel<<<2048, 256>>>(ei32, out, p_b2);
    count_kernel<<<(NE + 255) / 256, 256>>>();
    split_kernel<<<(NN * 512 + 255) / 256, 256>>>(x, NN * 512, XFh, XFl);

    GP a{};
    dim3 blk(256);

    // ---- batch: U = x@W1a, V = x@W1b, P = x@Wm_a ----
    a = GP{};
    a.M = NN; a.nch = 16; a.Kpad = 512;
    a.A0h = XFh; a.A0l = XFl; a.w0 = 512; a.ld0 = 512;
    a.jwh[0] = WTH;              a.jwl[0] = WTL;              a.jcf[0] = U; a.jb[0] = nullptr;
    a.jwh[1] = WTH + 256 * 512;  a.jwl[1] = WTL + 256 * 512;  a.jcf[1] = V; a.jb[1] = nullptr;
    a.jwh[2] = WTH + 256 * 1280; a.jwl[2] = WTL + 256 * 1280; a.jcf[2] = P; a.jb[2] = nullptr;
    a.njobs = 3;
    P0<<<dim3(79, 3), blk, SMEM_SZ>>>(a);

    // ---- EA = (relu(U[src]+V[dst]+ea@W1c+b1)) @ e_w2_0 + b2  [COMB] ----
    a = GP{};
    a.M = NE; a.nch = 8; a.Kpad = 256;
    a.I0 = SRC; a.I1 = DST; a.w0 = 256;
    a.Uf = U; a.Vf = V; a.EAT = eattr;
    a.W1c = e_w1_0 + (size_t)1024 * 256; a.B1 = e_b1_0;
    a.WtH = WTH + 256 * 1024; a.WtL = WTL + 256 * 1024;
    a.bias = e_b2_0; a.Ch = EAh; a.Cl = EAl;
    PC<<<dim3(1250), blk, SMEM_SZ>>>(a);

    // ---- MSG = relu(EA@Wm_b + P[src] + bm) scattered (red.v2) into S[dst] ----
    a = GP{};
    a.M = NE; a.nch = 8; a.Kpad = 256;
    a.A0h = EAh; a.A0l = EAl; a.w0 = 256; a.ld0 = 256;
    a.WtH = WTH + 256 * 1792; a.WtL = WTL + 256 * 1792;
    a.bias = n_bm_0; a.G1 = P; a.IG1 = SRC; a.SDST = DST; a.Cf = S;
    P3<<<dim3(1250), blk, SMEM_SZ>>>(a);
    mean_kernel<<<NN, 256>>>();

    // ---- XH = relu([x, S] @ n_w1_0 + b) ----
    a = GP{};
    a.M = NN; a.nch = 24; a.Kpad = 768;
    a.A0h = XFh; a.A0l = XFl; a.w0 = 512; a.ld0 = 512;
    a.A1h = Shh; a.A1l = Sll; a.ld1 = 256;
    a.WtH = WTH + 256 * 2048; a.WtL = WTL + 256 * 2048;
    a.bias = n_b1_0; a.Ch = XHh; a.Cl = XHl;
    P1<<<dim3(79), blk, SMEM_SZ>>>(a);

    // ---- batch: U1 = XH@Wc_a + bc_a, V1 = XH@Wc_b + bc_b  (X1 composed away) ----
    a = GP{};
    a.M = NN; a.nch = 8; a.Kpad = 256;
    a.A0h = XHh; a.A0l = XHl; a.w0 = 256; a.ld0 = 256;
    a.jwh[0] = WTH + 256 * 3584; a.jwl[0] = WTL + 256 * 3584; a.jcf[0] = U; a.jb[0] = BC;
    a.jwh[1] = WTH + 256 * 3840; a.jwl[1] = WTL + 256 * 3840; a.jcf[1] = V; a.jb[1] = BC + 256;
    a.njobs = 2;
    P0<<<dim3(79, 2), blk, SMEM_SZ>>>(a);

    // ---- EH2 = relu(EA@W11c + U1[src] + V1[dst] + e_b1_1) ----
    a = GP{};
    a.M = NE; a.nch = 8; a.Kpad = 256;
    a.A0h = EAh; a.A0l = EAl; a.w0 = 256; a.ld0 = 256;
    a.WtH = WTH + 256 * 2816; a.WtL = WTL + 256 * 2816;
    a.bias = e_b1_1; a.G1 = U; a.IG1 = SRC; a.G2 = V; a.IG2 = DST;
    a.Ch = EHh; a.Cl = EHl;
    P4<<<dim3(1250), blk, SMEM_SZ>>>(a);

    // ---- out = relu([EH2,EA] @ Wpred + bc_p) . p_w2 + b2  [PRED composed K=512] ----
    a = GP{};
    a.M = NE; a.nch = 16; a.Kpad = 512;
    a.A0h = EHh; a.A0l = EHl; a.w0 = 256; a.ld0 = 256;
    a.A1h = EAh; a.A1l = EAl; a.ld1 = 256;
    a.WtH = WTH + 256 * 3072; a.WtL = WTL + 256 * 3072;
    a.bias = BC + 512; a.PW2 = p_w2; a.OutP = out;
    P6<<<dim3(1250), blk, SMEM_SZ>>>(a);

    (void)in_sizes; (void)n_in; (void)out_size;
}